// round 6
// baseline (speedup 1.0000x reference)
#include <cuda_runtime.h>

#define B_   2
#define N_   169
#define NN_  338
#define C_   256
#define H_   4
#define HC_  1024
#define L_   3

typedef unsigned long long ull;

// ---------------- scratch (device globals) ---------------------------------
__device__ float g_x[NN_ * C_];               // running node features
__device__ float g_xl[NN_ * HC_];             // x @ Wl + bl
__device__ float g_xr[NN_ * HC_];             // x @ Wr + br
__device__ float g_agg[B_ * H_ * N_ * C_];    // per-head aggregation partials
__device__ float g_h[NN_ * C_];               // post layernorm
__device__ float g_m[NN_ * 2 * C_];           // mlp hidden
__device__ float g_u[H_ * NN_];               // <att, xl_n> per head
__device__ float g_w[H_ * NN_];               // <att, xr_n> per head

// ---------------- u/w rank-1 terms: u[h,n]=<att_h, xl[n,h,:]>, w likewise ---
__global__ __launch_bounds__(128) void uw_kernel(const float* __restrict__ xl,
                                                 const float* __restrict__ xr,
                                                 const float* __restrict__ att_l,
                                                 float* __restrict__ u,
                                                 float* __restrict__ w)
{
    int n = blockIdx.x;
    int h = threadIdx.x >> 5, lane = threadIdx.x & 31;
    const float4* xlp = (const float4*)&xl[(size_t)n * HC_ + h * C_];
    const float4* xrp = (const float4*)&xr[(size_t)n * HC_ + h * C_];
    const float4* ap  = (const float4*)&att_l[h * C_];
    float su = 0.f, sw = 0.f;
#pragma unroll
    for (int i = 0; i < 2; i++) {
        float4 a = ap[lane + 32 * i];
        float4 vl = xlp[lane + 32 * i];
        float4 vr = xrp[lane + 32 * i];
        su += a.x * vl.x + a.y * vl.y + a.z * vl.z + a.w * vl.w;
        sw += a.x * vr.x + a.y * vr.y + a.z * vr.z + a.w * vr.w;
    }
#pragma unroll
    for (int o = 16; o; o >>= 1) {
        su += __shfl_xor_sync(0xffffffffu, su, o);
        sw += __shfl_xor_sync(0xffffffffu, sw, o);
    }
    if (lane == 0) {
        u[h * NN_ + n] = su;
        w[h * NN_ + n] = sw;
    }
}

// ---------------- fused logits + softmax + aggregation ----------------------
// grid (22 d-tiles, 8 bh), block 512 = 16 warps: warp = (d-row 0..7, half 0..1)
// logit(d,s) = 0.6*(u_s + w_d) + 0.4 * sum_c att_c * |xl[s,c]+xr[d,c]|
__global__ __launch_bounds__(512) void attn_agg_kernel(const float* __restrict__ xl,
                                                       const float* __restrict__ xr,
                                                       const float* __restrict__ att_l,
                                                       const float* __restrict__ u,
                                                       const float* __restrict__ w,
                                                       float* __restrict__ agg)
{
    __shared__ __align__(16) union {
        struct {
            float XR[8][40];
            float XLs[6][32][38];   // even stride: 8B-aligned rows, conflict-free LDS.64
            float A4[32];
        } pa;
        struct {
            float Xs[32][260];
        } pb;
    } un;
    __shared__ float AL[8][193];
    __shared__ float MX[8][2];
    __shared__ float SS[8][2];

    int tid = threadIdx.x;
    int lane = tid & 31;
    int wid = tid >> 5;
    int ty = wid >> 1;            // d-row 0..7
    int hf = wid & 1;             // st-half: bands {0,1,2} or {3,4,5}
    int dt = blockIdx.x, bh = blockIdx.y;
    int b = bh >> 2, h = bh & 3;
    int d = dt * 8 + ty;
    bool dok = d < N_;

    ull acc[3];
#pragma unroll
    for (int j = 0; j < 3; j++) acc[j] = 0ull;
    const ull msk = 0x7FFFFFFF7FFFFFFFULL;

    // ---------------- Phase A: |.| part of logits ----------------
    for (int ck = 0; ck < C_; ck += 32) {
        if (hf == 0)
            un.pa.XR[ty][lane] = dok ? xr[(size_t)(b * N_ + d) * HC_ + h * C_ + ck + lane] : 0.f;
        if (tid < 32) un.pa.A4[tid] = 0.4f * att_l[h * C_ + ck + tid];
#pragma unroll
        for (int i = 0; i < 6; i++) {
            int f = tid + 512 * i;          // 3072 float2 total
            int st = f >> 9;
            int rem = f & 511;
            int row = rem >> 4;
            int cc = (rem & 15) * 2;
            int s = st * 32 + row;
            float2 v = make_float2(0.f, 0.f);
            if (s < N_) v = *(const float2*)&xl[(size_t)(b * N_ + s) * HC_ + h * C_ + ck + cc];
            *(float2*)&un.pa.XLs[st][row][cc] = v;
        }
        __syncthreads();
#pragma unroll
        for (int c2 = 0; c2 < 16; c2++) {
            ull r  = *(const ull*)&un.pa.XR[ty][c2 * 2];
            ull a4 = *(const ull*)&un.pa.A4[c2 * 2];
#pragma unroll
            for (int j = 0; j < 3; j++) {
                ull l = *(const ull*)&un.pa.XLs[hf * 3 + j][lane][c2 * 2];
                ull s, m;
                asm("add.rn.f32x2 %0, %1, %2;" : "=l"(s) : "l"(l), "l"(r));
                asm("and.b64 %0, %1, %2;"      : "=l"(m) : "l"(s), "l"(msk));
                asm("fma.rn.f32x2 %0, %1, %2, %0;" : "+l"(acc[j]) : "l"(m), "l"(a4));
            }
        }
        __syncthreads();
    }

    // ---------------- softmax over s (2 warps per d-row) ----------------
    float w_d = dok ? w[h * NN_ + b * N_ + d] : 0.f;
    float lg[3];
    float mx = -1e30f;
#pragma unroll
    for (int j = 0; j < 3; j++) {
        ull a = acc[j];
        float lo = __uint_as_float((unsigned)(a & 0xffffffffu));
        float hi = __uint_as_float((unsigned)(a >> 32));
        int s = (hf * 3 + j) * 32 + lane;
        float uv = (s < N_) ? u[h * NN_ + b * N_ + s] : 0.f;
        float v = 0.6f * (uv + w_d) + lo + hi;
        if (s >= N_ || s == d) v = -1e30f;
        lg[j] = v;
        mx = fmaxf(mx, v);
    }
#pragma unroll
    for (int o = 16; o; o >>= 1) mx = fmaxf(mx, __shfl_xor_sync(0xffffffffu, mx, o));
    if (lane == 0) MX[ty][hf] = mx;
    __syncthreads();
    float gmx = fmaxf(MX[ty][0], MX[ty][1]);
    float sum = 0.f;
#pragma unroll
    for (int j = 0; j < 3; j++) {
        float e = __expf(lg[j] - gmx);
        lg[j] = e;
        sum += e;
    }
#pragma unroll
    for (int o = 16; o; o >>= 1) sum += __shfl_xor_sync(0xffffffffu, sum, o);
    if (lane == 0) SS[ty][hf] = sum;
    __syncthreads();
    float inv = 1.f / (SS[ty][0] + SS[ty][1] + 1e-16f);
#pragma unroll
    for (int j = 0; j < 3; j++)
        AL[ty][(hf * 3 + j) * 32 + lane] = lg[j] * inv;     // zeros for s>=169
    __syncthreads();

    // ---------------- Phase B: agg GEMM 8d x 256c x 192s ----------------
    // warp (ty,hf) accumulates c in [hf*128, hf*128+128)
    float4 acc0 = make_float4(0.f, 0.f, 0.f, 0.f);
    int cb = hf * 128 + lane * 4;
    for (int sk = 0; sk < 192; sk += 32) {
#pragma unroll
        for (int i = 0; i < 4; i++) {
            int f = tid + 512 * i;          // 2048 float4 total
            int row = f >> 6, col4 = f & 63;
            int s = sk + row;
            float4 v = make_float4(0.f, 0.f, 0.f, 0.f);
            if (s < N_) v = *(const float4*)&xl[(size_t)(b * N_ + s) * HC_ + h * C_ + col4 * 4];
            *(float4*)&un.pb.Xs[row][col4 * 4] = v;
        }
        __syncthreads();
#pragma unroll
        for (int k = 0; k < 32; k++) {
            float av = AL[ty][sk + k];
            float4 x0 = *(const float4*)&un.pb.Xs[k][cb];
            acc0.x = fmaf(av, x0.x, acc0.x); acc0.y = fmaf(av, x0.y, acc0.y);
            acc0.z = fmaf(av, x0.z, acc0.z); acc0.w = fmaf(av, x0.w, acc0.w);
        }
        __syncthreads();
    }

    if (dok)
        *(float4*)&agg[((size_t)bh * N_ + d) * C_ + cb] = acc0;
}

// ---------------- fused xl/xr GEMM: 64x32 tile, kk=32, 4x2 per thread -------
__global__ __launch_bounds__(256) void gemm_dual(const float* __restrict__ A,
                                                 const float* __restrict__ B1,
                                                 const float* __restrict__ c1,
                                                 float* __restrict__ o1,
                                                 const float* __restrict__ B2,
                                                 const float* __restrict__ c2p,
                                                 float* __restrict__ o2,
                                                 int M, int K)
{
    __shared__ __align__(16) float As[32][68];
    __shared__ __align__(16) float Bs[32][33];

    const float* Bm;
    const float* bias;
    float* out;
    int n0;
    if (blockIdx.x < 32) { Bm = B1; bias = c1;  out = o1; n0 = blockIdx.x * 32; }
    else                 { Bm = B2; bias = c2p; out = o2; n0 = (blockIdx.x - 32) * 32; }

    int tid = threadIdx.x;
    int tx = tid & 15, ty = tid >> 4;
    int m0 = blockIdx.y * 64;
    int lm = tid & 63, kq = tid >> 6;
    int br = tid >> 3, bc = (tid & 7) * 4;

    float acc[4][2];
#pragma unroll
    for (int i = 0; i < 4; i++) { acc[i][0] = 0.f; acc[i][1] = 0.f; }

    for (int kk = 0; kk < K; kk += 32) {
#pragma unroll
        for (int q = 0; q < 2; q++) {
            int kb = (kq + q * 4) * 4;
            float4 f = make_float4(0.f, 0.f, 0.f, 0.f);
            if (m0 + lm < M) f = *(const float4*)&A[(size_t)(m0 + lm) * K + kk + kb];
            As[kb + 0][lm] = f.x;
            As[kb + 1][lm] = f.y;
            As[kb + 2][lm] = f.z;
            As[kb + 3][lm] = f.w;
        }
        {
            float4 f = *(const float4*)&Bm[(size_t)(kk + br) * HC_ + n0 + bc];
            Bs[br][bc + 0] = f.x;
            Bs[br][bc + 1] = f.y;
            Bs[br][bc + 2] = f.z;
            Bs[br][bc + 3] = f.w;
        }
        __syncthreads();
#pragma unroll
        for (int k = 0; k < 32; k++) {
            float4 a = *(const float4*)&As[k][ty * 4];
            float bv0 = Bs[k][tx * 2], bv1 = Bs[k][tx * 2 + 1];
            acc[0][0] = fmaf(a.x, bv0, acc[0][0]); acc[0][1] = fmaf(a.x, bv1, acc[0][1]);
            acc[1][0] = fmaf(a.y, bv0, acc[1][0]); acc[1][1] = fmaf(a.y, bv1, acc[1][1]);
            acc[2][0] = fmaf(a.z, bv0, acc[2][0]); acc[2][1] = fmaf(a.z, bv1, acc[2][1]);
            acc[3][0] = fmaf(a.w, bv0, acc[3][0]); acc[3][1] = fmaf(a.w, bv1, acc[3][1]);
        }
        __syncthreads();
    }

    float b0 = bias[n0 + tx * 2], b1 = bias[n0 + tx * 2 + 1];
#pragma unroll
    for (int i = 0; i < 4; i++) {
        int r = m0 + ty * 4 + i;
        if (r < M) {
            out[(size_t)r * HC_ + n0 + tx * 2]     = acc[i][0] + b0;
            out[(size_t)r * HC_ + n0 + tx * 2 + 1] = acc[i][1] + b1;
        }
    }
}

// ---------------- generic 32x32 tiled fp32 GEMM (MLP path) ------------------
// mode: 1 relu, 2 residual +=
__global__ void gemm_kernel(const float* __restrict__ A,
                            const float* __restrict__ Bm,
                            const float* __restrict__ bias,
                            float* __restrict__ out,
                            int M, int N, int K, int mode)
{
    __shared__ float As[32][33];
    __shared__ float Bs[32][33];
    int tid = threadIdx.x;
    int tx = tid & 15, ty = tid >> 4;
    int m0 = blockIdx.y * 32;
    int n0 = blockIdx.x * 32;
    int lr = tid >> 3, lc = (tid & 7) * 4;
    float a00 = 0.f, a01 = 0.f, a10 = 0.f, a11 = 0.f;

    for (int kk = 0; kk < K; kk += 32) {
        {
            float4 f = make_float4(0.f, 0.f, 0.f, 0.f);
            if (m0 + lr < M) f = *(const float4*)&A[(size_t)(m0 + lr) * K + kk + lc];
            As[lr][lc + 0] = f.x; As[lr][lc + 1] = f.y;
            As[lr][lc + 2] = f.z; As[lr][lc + 3] = f.w;
            float4 g = *(const float4*)&Bm[(size_t)(kk + lr) * N + n0 + lc];
            Bs[lr][lc + 0] = g.x; Bs[lr][lc + 1] = g.y;
            Bs[lr][lc + 2] = g.z; Bs[lr][lc + 3] = g.w;
        }
        __syncthreads();
#pragma unroll
        for (int k = 0; k < 32; k++) {
            float av0 = As[ty][k],      av1 = As[ty + 16][k];
            float bv0 = Bs[k][tx],      bv1 = Bs[k][tx + 16];
            a00 = fmaf(av0, bv0, a00);  a01 = fmaf(av0, bv1, a01);
            a10 = fmaf(av1, bv0, a10);  a11 = fmaf(av1, bv1, a11);
        }
        __syncthreads();
    }

    int r0 = m0 + ty, r1 = m0 + ty + 16;
    int c0 = n0 + tx, c1 = n0 + tx + 16;
    float b0 = bias[c0], b1 = bias[c1];
    if (mode == 1) {
        if (r0 < M) { out[r0 * N + c0] = fmaxf(a00 + b0, 0.f); out[r0 * N + c1] = fmaxf(a01 + b1, 0.f); }
        if (r1 < M) { out[r1 * N + c0] = fmaxf(a10 + b0, 0.f); out[r1 * N + c1] = fmaxf(a11 + b1, 0.f); }
    } else {
        if (r0 < M) { out[r0 * N + c0] += a00 + b0; out[r0 * N + c1] += a01 + b1; }
        if (r1 < M) { out[r1 * N + c0] += a10 + b0; out[r1 * N + c1] += a11 + b1; }
    }
}

// ---------------- head-mean + bias + layernorm (4 rows/block, float4) -------
__global__ __launch_bounds__(256) void ln_kernel(const float* __restrict__ agg,
                                                 const float* __restrict__ bias_l,
                                                 const float* __restrict__ g,
                                                 const float* __restrict__ bt,
                                                 float* __restrict__ out)
{
    int ty = threadIdx.x >> 6;
    int tx = threadIdx.x & 63;
    int wq = threadIdx.x >> 5;
    int n = blockIdx.x * 4 + ty;
    bool ok = n < NN_;
    int b = (n >= N_) ? 1 : 0;
    int d = n - b * N_;

    float4 v = make_float4(0.f, 0.f, 0.f, 0.f);
    if (ok) {
#pragma unroll
        for (int h = 0; h < H_; h++) {
            float4 t = *(const float4*)&agg[((size_t)(b * H_ + h) * N_ + d) * C_ + tx * 4];
            v.x += t.x; v.y += t.y; v.z += t.z; v.w += t.w;
        }
        float4 bb = *(const float4*)&bias_l[tx * 4];
        v.x = 0.25f * v.x + bb.x; v.y = 0.25f * v.y + bb.y;
        v.z = 0.25f * v.z + bb.z; v.w = 0.25f * v.w + bb.w;
    }

    __shared__ float red[8];
    float s = v.x + v.y + v.z + v.w;
#pragma unroll
    for (int o = 16; o; o >>= 1) s += __shfl_xor_sync(0xffffffffu, s, o);
    if ((threadIdx.x & 31) == 0) red[wq] = s;
    __syncthreads();
    float mu = (red[ty * 2] + red[ty * 2 + 1]) * (1.f / C_);
    __syncthreads();

    float4 dd = make_float4(v.x - mu, v.y - mu, v.z - mu, v.w - mu);
    float s2 = dd.x * dd.x + dd.y * dd.y + dd.z * dd.z + dd.w * dd.w;
#pragma unroll
    for (int o = 16; o; o >>= 1) s2 += __shfl_xor_sync(0xffffffffu, s2, o);
    if ((threadIdx.x & 31) == 0) red[wq] = s2;
    __syncthreads();
    float rstd = rsqrtf((red[ty * 2] + red[ty * 2 + 1]) * (1.f / C_) + 1e-5f);

    if (ok) {
        float4 gg = *(const float4*)&g[tx * 4];
        float4 tb = *(const float4*)&bt[tx * 4];
        float4 o4;
        o4.x = dd.x * rstd * gg.x + tb.x;
        o4.y = dd.y * rstd * gg.y + tb.y;
        o4.z = dd.z * rstd * gg.z + tb.z;
        o4.w = dd.w * rstd * gg.w + tb.w;
        *(float4*)&out[(size_t)n * C_ + tx * 4] = o4;
    }
}

// ---------------- final mean pool per graph ----------------------------------
__global__ void pool_kernel(const float* __restrict__ x, float* __restrict__ out)
{
    int b = blockIdx.x, t = threadIdx.x;
    float s = 0.f;
#pragma unroll 13
    for (int d = 0; d < N_; d++) s += x[(b * N_ + d) * C_ + t];
    out[b * C_ + t] = s * (1.f / N_);
}

__global__ void copy_kernel(const float* __restrict__ src, float* __restrict__ dst)
{
    int i = blockIdx.x * 256 + threadIdx.x;
    dst[i] = src[i];
}

// ---------------- host launcher -----------------------------------------------
extern "C" void kernel_launch(void* const* d_in, const int* in_sizes, int n_in,
                              void* d_out, int out_size)
{
    const float* x    = (const float*)d_in[0];
    const float* Wl   = (const float*)d_in[1];
    const float* bl   = (const float*)d_in[2];
    const float* Wr   = (const float*)d_in[3];
    const float* br   = (const float*)d_in[4];
    const float* att  = (const float*)d_in[5];
    const float* bias = (const float*)d_in[6];
    const float* lng  = (const float*)d_in[7];
    const float* lnb  = (const float*)d_in[8];
    const float* W1   = (const float*)d_in[9];
    const float* b1   = (const float*)d_in[10];
    const float* W2   = (const float*)d_in[11];
    const float* b2   = (const float*)d_in[12];

    float *bx, *bxl, *bxr, *bag, *bh, *bm, *bu, *bw;
    cudaGetSymbolAddress((void**)&bx,  g_x);
    cudaGetSymbolAddress((void**)&bxl, g_xl);
    cudaGetSymbolAddress((void**)&bxr, g_xr);
    cudaGetSymbolAddress((void**)&bag, g_agg);
    cudaGetSymbolAddress((void**)&bh,  g_h);
    cudaGetSymbolAddress((void**)&bm,  g_m);
    cudaGetSymbolAddress((void**)&bu,  g_u);
    cudaGetSymbolAddress((void**)&bw,  g_w);

    copy_kernel<<<NN_, 256>>>(x, bx);

    for (int l = 0; l < L_; l++) {
        gemm_dual<<<dim3(64, 6), 256>>>(bx,
                                        Wl + l * C_ * HC_, bl + l * HC_, bxl,
                                        Wr + l * C_ * HC_, br + l * HC_, bxr,
                                        NN_, C_);
        uw_kernel<<<NN_, 128>>>(bxl, bxr, att + l * H_ * C_, bu, bw);
        attn_agg_kernel<<<dim3(22, 8), 512>>>(bxl, bxr, att + l * H_ * C_, bu, bw, bag);
        ln_kernel<<<85, 256>>>(bag, bias + l * C_, lng + l * C_, lnb + l * C_, bh);
        gemm_kernel<<<dim3(16, 11), 256>>>(bh, W1 + l * C_ * 2 * C_, b1 + l * 2 * C_,
                                           bm, NN_, 2 * C_, C_, 1);
        gemm_kernel<<<dim3(8, 11), 256>>>(bm, W2 + l * 2 * C_ * C_, b2 + l * C_,
                                          bx, NN_, C_, 2 * C_, 2);
    }

    pool_kernel<<<B_, 256>>>(bx, (float*)d_out);
}

// round 7
// speedup vs baseline: 1.0723x; 1.0723x over previous
#include <cuda_runtime.h>

#define B_   2
#define N_   169
#define NN_  338
#define C_   256
#define H_   4
#define HC_  1024
#define L_   3

typedef unsigned long long ull;

// ---------------- scratch (device globals) ---------------------------------
__device__ float g_x[NN_ * C_];               // running node features
__device__ float g_xl[NN_ * HC_];             // x @ Wl + bl
__device__ float g_xr[NN_ * HC_];             // x @ Wr + br
__device__ float g_agg[B_ * H_ * N_ * C_];    // per-head aggregation partials
__device__ float g_h[NN_ * C_];               // post layernorm
__device__ float g_m[NN_ * 2 * C_];           // mlp hidden
__device__ float g_u[H_ * NN_];               // <att, xl_n> per head
__device__ float g_w[H_ * NN_];               // <att, xr_n> per head

// ---------------- u/w rank-1 terms: u[h,n]=<att_h, xl[n,h,:]>, w likewise ---
__global__ __launch_bounds__(128) void uw_kernel(const float* __restrict__ xl,
                                                 const float* __restrict__ xr,
                                                 const float* __restrict__ att_l,
                                                 float* __restrict__ u,
                                                 float* __restrict__ w)
{
    int n = blockIdx.x;
    int h = threadIdx.x >> 5, lane = threadIdx.x & 31;
    const float4* xlp = (const float4*)&xl[(size_t)n * HC_ + h * C_];
    const float4* xrp = (const float4*)&xr[(size_t)n * HC_ + h * C_];
    const float4* ap  = (const float4*)&att_l[h * C_];
    float su = 0.f, sw = 0.f;
#pragma unroll
    for (int i = 0; i < 2; i++) {
        float4 a = ap[lane + 32 * i];
        float4 vl = xlp[lane + 32 * i];
        float4 vr = xrp[lane + 32 * i];
        su += a.x * vl.x + a.y * vl.y + a.z * vl.z + a.w * vl.w;
        sw += a.x * vr.x + a.y * vr.y + a.z * vr.z + a.w * vr.w;
    }
#pragma unroll
    for (int o = 16; o; o >>= 1) {
        su += __shfl_xor_sync(0xffffffffu, su, o);
        sw += __shfl_xor_sync(0xffffffffu, sw, o);
    }
    if (lane == 0) {
        u[h * NN_ + n] = su;
        w[h * NN_ + n] = sw;
    }
}

// ---------------- fused logits + softmax + aggregation ----------------------
// grid (43 d-tiles, 8 bh), block 128 = 4 warps, warp = one d-row.
// ~2.3 blocks/SM co-resident -> cross-block latency hiding at barriers.
// logit(d,s) = 0.6*(u_s + w_d) + 0.4 * sum_c att_c * |xl[s,c]+xr[d,c]|
__global__ __launch_bounds__(128) void attn_agg_kernel(const float* __restrict__ xl,
                                                       const float* __restrict__ xr,
                                                       const float* __restrict__ att_l,
                                                       const float* __restrict__ u,
                                                       const float* __restrict__ w,
                                                       float* __restrict__ agg)
{
    __shared__ __align__(16) union {
        struct {
            float XR[4][40];
            float XLs[6][32][38];   // even stride: 8B-aligned rows, conflict-free LDS.64
            float A4[32];
        } pa;
        struct {
            float Xs[32][260];
        } pb;
    } un;
    __shared__ float AL[4][193];

    int tid = threadIdx.x;
    int lane = tid & 31;
    int ty = tid >> 5;            // warp = d-row 0..3
    int dt = blockIdx.x, bh = blockIdx.y;
    int b = bh >> 2, h = bh & 3;
    int d = dt * 4 + ty;
    bool dok = d < N_;

    ull acc[6];
#pragma unroll
    for (int st = 0; st < 6; st++) acc[st] = 0ull;
    const ull msk = 0x7FFFFFFF7FFFFFFFULL;

    // ---------------- Phase A: |.| part of logits ----------------
    for (int ck = 0; ck < C_; ck += 32) {
        un.pa.XR[ty][lane] = dok ? xr[(size_t)(b * N_ + d) * HC_ + h * C_ + ck + lane] : 0.f;
        if (tid < 32) un.pa.A4[tid] = 0.4f * att_l[h * C_ + ck + tid];
#pragma unroll
        for (int i = 0; i < 24; i++) {
            int f = tid + 128 * i;          // 3072 float2 total
            int st = f >> 9;
            int rem = f & 511;
            int row = rem >> 4;
            int cc = (rem & 15) * 2;
            int s = st * 32 + row;
            float2 v = make_float2(0.f, 0.f);
            if (s < N_) v = *(const float2*)&xl[(size_t)(b * N_ + s) * HC_ + h * C_ + ck + cc];
            *(float2*)&un.pa.XLs[st][row][cc] = v;
        }
        __syncthreads();
#pragma unroll
        for (int c2 = 0; c2 < 16; c2++) {
            ull r  = *(const ull*)&un.pa.XR[ty][c2 * 2];
            ull a4 = *(const ull*)&un.pa.A4[c2 * 2];
#pragma unroll
            for (int j = 0; j < 6; j++) {
                ull l = *(const ull*)&un.pa.XLs[j][lane][c2 * 2];
                ull s, m;
                asm("add.rn.f32x2 %0, %1, %2;" : "=l"(s) : "l"(l), "l"(r));
                asm("and.b64 %0, %1, %2;"      : "=l"(m) : "l"(s), "l"(msk));
                asm("fma.rn.f32x2 %0, %1, %2, %0;" : "+l"(acc[j]) : "l"(m), "l"(a4));
            }
        }
        __syncthreads();
    }

    // ---------------- softmax over s (one warp per d-row) ----------------
    float w_d = dok ? w[h * NN_ + b * N_ + d] : 0.f;
    float lg[6];
    float mx = -1e30f;
#pragma unroll
    for (int j = 0; j < 6; j++) {
        ull a = acc[j];
        float lo = __uint_as_float((unsigned)(a & 0xffffffffu));
        float hi = __uint_as_float((unsigned)(a >> 32));
        int s = j * 32 + lane;
        float uv = (s < N_) ? u[h * NN_ + b * N_ + s] : 0.f;
        float v = 0.6f * (uv + w_d) + lo + hi;
        if (s >= N_ || s == d) v = -1e30f;
        lg[j] = v;
        mx = fmaxf(mx, v);
    }
#pragma unroll
    for (int o = 16; o; o >>= 1) mx = fmaxf(mx, __shfl_xor_sync(0xffffffffu, mx, o));
    float sum = 0.f;
#pragma unroll
    for (int j = 0; j < 6; j++) {
        float e = __expf(lg[j] - mx);
        lg[j] = e;
        sum += e;
    }
#pragma unroll
    for (int o = 16; o; o >>= 1) sum += __shfl_xor_sync(0xffffffffu, sum, o);
    float inv = 1.f / (sum + 1e-16f);
#pragma unroll
    for (int j = 0; j < 6; j++)
        AL[ty][j * 32 + lane] = lg[j] * inv;     // zeros for s>=169
    __syncthreads();

    // ---------------- Phase B: agg GEMM 4d x 256c x 192s ----------------
    float4 acc0 = make_float4(0.f, 0.f, 0.f, 0.f);
    float4 acc1 = make_float4(0.f, 0.f, 0.f, 0.f);
    for (int sk = 0; sk < 192; sk += 32) {
#pragma unroll
        for (int i = 0; i < 16; i++) {
            int f = tid + 128 * i;          // 2048 float4 total
            int row = f >> 6, col4 = f & 63;
            int s = sk + row;
            float4 v = make_float4(0.f, 0.f, 0.f, 0.f);
            if (s < N_) v = *(const float4*)&xl[(size_t)(b * N_ + s) * HC_ + h * C_ + col4 * 4];
            *(float4*)&un.pb.Xs[row][col4 * 4] = v;
        }
        __syncthreads();
#pragma unroll
        for (int k = 0; k < 32; k++) {
            float av = AL[ty][sk + k];
            float4 x0 = *(const float4*)&un.pb.Xs[k][lane * 4];
            float4 x1 = *(const float4*)&un.pb.Xs[k][lane * 4 + 128];
            acc0.x = fmaf(av, x0.x, acc0.x); acc0.y = fmaf(av, x0.y, acc0.y);
            acc0.z = fmaf(av, x0.z, acc0.z); acc0.w = fmaf(av, x0.w, acc0.w);
            acc1.x = fmaf(av, x1.x, acc1.x); acc1.y = fmaf(av, x1.y, acc1.y);
            acc1.z = fmaf(av, x1.z, acc1.z); acc1.w = fmaf(av, x1.w, acc1.w);
        }
        __syncthreads();
    }

    if (dok) {
        float* o = agg + ((size_t)bh * N_ + d) * C_;
        *(float4*)&o[lane * 4]       = acc0;
        *(float4*)&o[lane * 4 + 128] = acc1;
    }
}

// ---------------- fused xl/xr GEMM: 64x32 tile, kk=32, 4x2 per thread -------
__global__ __launch_bounds__(256) void gemm_dual(const float* __restrict__ A,
                                                 const float* __restrict__ B1,
                                                 const float* __restrict__ c1,
                                                 float* __restrict__ o1,
                                                 const float* __restrict__ B2,
                                                 const float* __restrict__ c2p,
                                                 float* __restrict__ o2,
                                                 int M, int K)
{
    __shared__ __align__(16) float As[32][68];
    __shared__ __align__(16) float Bs[32][33];

    const float* Bm;
    const float* bias;
    float* out;
    int n0;
    if (blockIdx.x < 32) { Bm = B1; bias = c1;  out = o1; n0 = blockIdx.x * 32; }
    else                 { Bm = B2; bias = c2p; out = o2; n0 = (blockIdx.x - 32) * 32; }

    int tid = threadIdx.x;
    int tx = tid & 15, ty = tid >> 4;
    int m0 = blockIdx.y * 64;
    int lm = tid & 63, kq = tid >> 6;
    int br = tid >> 3, bc = (tid & 7) * 4;

    float acc[4][2];
#pragma unroll
    for (int i = 0; i < 4; i++) { acc[i][0] = 0.f; acc[i][1] = 0.f; }

    for (int kk = 0; kk < K; kk += 32) {
#pragma unroll
        for (int q = 0; q < 2; q++) {
            int kb = (kq + q * 4) * 4;
            float4 f = make_float4(0.f, 0.f, 0.f, 0.f);
            if (m0 + lm < M) f = *(const float4*)&A[(size_t)(m0 + lm) * K + kk + kb];
            As[kb + 0][lm] = f.x;
            As[kb + 1][lm] = f.y;
            As[kb + 2][lm] = f.z;
            As[kb + 3][lm] = f.w;
        }
        {
            float4 f = *(const float4*)&Bm[(size_t)(kk + br) * HC_ + n0 + bc];
            Bs[br][bc + 0] = f.x;
            Bs[br][bc + 1] = f.y;
            Bs[br][bc + 2] = f.z;
            Bs[br][bc + 3] = f.w;
        }
        __syncthreads();
#pragma unroll
        for (int k = 0; k < 32; k++) {
            float4 a = *(const float4*)&As[k][ty * 4];
            float bv0 = Bs[k][tx * 2], bv1 = Bs[k][tx * 2 + 1];
            acc[0][0] = fmaf(a.x, bv0, acc[0][0]); acc[0][1] = fmaf(a.x, bv1, acc[0][1]);
            acc[1][0] = fmaf(a.y, bv0, acc[1][0]); acc[1][1] = fmaf(a.y, bv1, acc[1][1]);
            acc[2][0] = fmaf(a.z, bv0, acc[2][0]); acc[2][1] = fmaf(a.z, bv1, acc[2][1]);
            acc[3][0] = fmaf(a.w, bv0, acc[3][0]); acc[3][1] = fmaf(a.w, bv1, acc[3][1]);
        }
        __syncthreads();
    }

    float b0 = bias[n0 + tx * 2], b1 = bias[n0 + tx * 2 + 1];
#pragma unroll
    for (int i = 0; i < 4; i++) {
        int r = m0 + ty * 4 + i;
        if (r < M) {
            out[(size_t)r * HC_ + n0 + tx * 2]     = acc[i][0] + b0;
            out[(size_t)r * HC_ + n0 + tx * 2 + 1] = acc[i][1] + b1;
        }
    }
}

// ---------------- generic 32x32 tiled fp32 GEMM (MLP path) ------------------
// mode: 1 relu, 2 residual +=
__global__ void gemm_kernel(const float* __restrict__ A,
                            const float* __restrict__ Bm,
                            const float* __restrict__ bias,
                            float* __restrict__ out,
                            int M, int N, int K, int mode)
{
    __shared__ float As[32][33];
    __shared__ float Bs[32][33];
    int tid = threadIdx.x;
    int tx = tid & 15, ty = tid >> 4;
    int m0 = blockIdx.y * 32;
    int n0 = blockIdx.x * 32;
    int lr = tid >> 3, lc = (tid & 7) * 4;
    float a00 = 0.f, a01 = 0.f, a10 = 0.f, a11 = 0.f;

    for (int kk = 0; kk < K; kk += 32) {
        {
            float4 f = make_float4(0.f, 0.f, 0.f, 0.f);
            if (m0 + lr < M) f = *(const float4*)&A[(size_t)(m0 + lr) * K + kk + lc];
            As[lr][lc + 0] = f.x; As[lr][lc + 1] = f.y;
            As[lr][lc + 2] = f.z; As[lr][lc + 3] = f.w;
            float4 g = *(const float4*)&Bm[(size_t)(kk + lr) * N + n0 + lc];
            Bs[lr][lc + 0] = g.x; Bs[lr][lc + 1] = g.y;
            Bs[lr][lc + 2] = g.z; Bs[lr][lc + 3] = g.w;
        }
        __syncthreads();
#pragma unroll
        for (int k = 0; k < 32; k++) {
            float av0 = As[ty][k],      av1 = As[ty + 16][k];
            float bv0 = Bs[k][tx],      bv1 = Bs[k][tx + 16];
            a00 = fmaf(av0, bv0, a00);  a01 = fmaf(av0, bv1, a01);
            a10 = fmaf(av1, bv0, a10);  a11 = fmaf(av1, bv1, a11);
        }
        __syncthreads();
    }

    int r0 = m0 + ty, r1 = m0 + ty + 16;
    int c0 = n0 + tx, c1 = n0 + tx + 16;
    float b0 = bias[c0], b1 = bias[c1];
    if (mode == 1) {
        if (r0 < M) { out[r0 * N + c0] = fmaxf(a00 + b0, 0.f); out[r0 * N + c1] = fmaxf(a01 + b1, 0.f); }
        if (r1 < M) { out[r1 * N + c0] = fmaxf(a10 + b0, 0.f); out[r1 * N + c1] = fmaxf(a11 + b1, 0.f); }
    } else {
        if (r0 < M) { out[r0 * N + c0] += a00 + b0; out[r0 * N + c1] += a01 + b1; }
        if (r1 < M) { out[r1 * N + c0] += a10 + b0; out[r1 * N + c1] += a11 + b1; }
    }
}

// ---------------- head-mean + bias + layernorm (4 rows/block, float4) -------
__global__ __launch_bounds__(256) void ln_kernel(const float* __restrict__ agg,
                                                 const float* __restrict__ bias_l,
                                                 const float* __restrict__ g,
                                                 const float* __restrict__ bt,
                                                 float* __restrict__ out)
{
    int ty = threadIdx.x >> 6;
    int tx = threadIdx.x & 63;
    int wq = threadIdx.x >> 5;
    int n = blockIdx.x * 4 + ty;
    bool ok = n < NN_;
    int b = (n >= N_) ? 1 : 0;
    int d = n - b * N_;

    float4 v = make_float4(0.f, 0.f, 0.f, 0.f);
    if (ok) {
#pragma unroll
        for (int h = 0; h < H_; h++) {
            float4 t = *(const float4*)&agg[((size_t)(b * H_ + h) * N_ + d) * C_ + tx * 4];
            v.x += t.x; v.y += t.y; v.z += t.z; v.w += t.w;
        }
        float4 bb = *(const float4*)&bias_l[tx * 4];
        v.x = 0.25f * v.x + bb.x; v.y = 0.25f * v.y + bb.y;
        v.z = 0.25f * v.z + bb.z; v.w = 0.25f * v.w + bb.w;
    }

    __shared__ float red[8];
    float s = v.x + v.y + v.z + v.w;
#pragma unroll
    for (int o = 16; o; o >>= 1) s += __shfl_xor_sync(0xffffffffu, s, o);
    if ((threadIdx.x & 31) == 0) red[wq] = s;
    __syncthreads();
    float mu = (red[ty * 2] + red[ty * 2 + 1]) * (1.f / C_);
    __syncthreads();

    float4 dd = make_float4(v.x - mu, v.y - mu, v.z - mu, v.w - mu);
    float s2 = dd.x * dd.x + dd.y * dd.y + dd.z * dd.z + dd.w * dd.w;
#pragma unroll
    for (int o = 16; o; o >>= 1) s2 += __shfl_xor_sync(0xffffffffu, s2, o);
    if ((threadIdx.x & 31) == 0) red[wq] = s2;
    __syncthreads();
    float rstd = rsqrtf((red[ty * 2] + red[ty * 2 + 1]) * (1.f / C_) + 1e-5f);

    if (ok) {
        float4 gg = *(const float4*)&g[tx * 4];
        float4 tb = *(const float4*)&bt[tx * 4];
        float4 o4;
        o4.x = dd.x * rstd * gg.x + tb.x;
        o4.y = dd.y * rstd * gg.y + tb.y;
        o4.z = dd.z * rstd * gg.z + tb.z;
        o4.w = dd.w * rstd * gg.w + tb.w;
        *(float4*)&out[(size_t)n * C_ + tx * 4] = o4;
    }
}

// ---------------- final mean pool per graph ----------------------------------
__global__ void pool_kernel(const float* __restrict__ x, float* __restrict__ out)
{
    int b = blockIdx.x, t = threadIdx.x;
    float s = 0.f;
#pragma unroll 13
    for (int d = 0; d < N_; d++) s += x[(b * N_ + d) * C_ + t];
    out[b * C_ + t] = s * (1.f / N_);
}

__global__ void copy_kernel(const float* __restrict__ src, float* __restrict__ dst)
{
    int i = blockIdx.x * 256 + threadIdx.x;
    dst[i] = src[i];
}

// ---------------- host launcher -----------------------------------------------
extern "C" void kernel_launch(void* const* d_in, const int* in_sizes, int n_in,
                              void* d_out, int out_size)
{
    const float* x    = (const float*)d_in[0];
    const float* Wl   = (const float*)d_in[1];
    const float* bl   = (const float*)d_in[2];
    const float* Wr   = (const float*)d_in[3];
    const float* br   = (const float*)d_in[4];
    const float* att  = (const float*)d_in[5];
    const float* bias = (const float*)d_in[6];
    const float* lng  = (const float*)d_in[7];
    const float* lnb  = (const float*)d_in[8];
    const float* W1   = (const float*)d_in[9];
    const float* b1   = (const float*)d_in[10];
    const float* W2   = (const float*)d_in[11];
    const float* b2   = (const float*)d_in[12];

    float *bx, *bxl, *bxr, *bag, *bh, *bm, *bu, *bw;
    cudaGetSymbolAddress((void**)&bx,  g_x);
    cudaGetSymbolAddress((void**)&bxl, g_xl);
    cudaGetSymbolAddress((void**)&bxr, g_xr);
    cudaGetSymbolAddress((void**)&bag, g_agg);
    cudaGetSymbolAddress((void**)&bh,  g_h);
    cudaGetSymbolAddress((void**)&bm,  g_m);
    cudaGetSymbolAddress((void**)&bu,  g_u);
    cudaGetSymbolAddress((void**)&bw,  g_w);

    copy_kernel<<<NN_, 256>>>(x, bx);

    for (int l = 0; l < L_; l++) {
        gemm_dual<<<dim3(64, 6), 256>>>(bx,
                                        Wl + l * C_ * HC_, bl + l * HC_, bxl,
                                        Wr + l * C_ * HC_, br + l * HC_, bxr,
                                        NN_, C_);
        uw_kernel<<<NN_, 128>>>(bxl, bxr, att + l * H_ * C_, bu, bw);
        attn_agg_kernel<<<dim3(43, 8), 128>>>(bxl, bxr, att + l * H_ * C_, bu, bw, bag);
        ln_kernel<<<85, 256>>>(bag, bias + l * C_, lng + l * C_, lnb + l * C_, bh);
        gemm_kernel<<<dim3(16, 11), 256>>>(bh, W1 + l * C_ * 2 * C_, b1 + l * 2 * C_,
                                           bm, NN_, 2 * C_, C_, 1);
        gemm_kernel<<<dim3(8, 11), 256>>>(bm, W2 + l * 2 * C_ * C_, b2 + l * C_,
                                          bx, NN_, C_, 2 * C_, 2);
    }

    pool_kernel<<<B_, 256>>>(bx, (float*)d_out);
}

// round 8
// speedup vs baseline: 1.1375x; 1.0608x over previous
#include <cuda_runtime.h>

#define B_   2
#define N_   169
#define NN_  338
#define C_   256
#define H_   4
#define HC_  1024
#define L_   3

typedef unsigned long long ull;

// ---------------- scratch (device globals) ---------------------------------
__device__ float g_x[NN_ * C_];               // running node features
__device__ float g_xl[NN_ * HC_];             // x @ Wl + bl
__device__ float g_xr[NN_ * HC_];             // x @ Wr + br
__device__ float g_agg[B_ * H_ * N_ * C_];    // per-head aggregation partials
__device__ float g_h[NN_ * C_];               // post layernorm
__device__ float g_m[NN_ * 2 * C_];           // mlp hidden
__device__ float g_u[H_ * NN_];               // <att, xl_n> per head
__device__ float g_w[H_ * NN_];               // <att, xr_n> per head

// ---------------- cp.async helpers ------------------------------------------
__device__ __forceinline__ unsigned s2u(const void* p)
{
    return (unsigned)__cvta_generic_to_shared(p);
}
__device__ __forceinline__ void cp8(unsigned dst, const void* src, bool ok)
{
    int sz = ok ? 8 : 0;
    asm volatile("cp.async.ca.shared.global [%0], [%1], 8, %2;"
                 :: "r"(dst), "l"(src), "r"(sz));
}
__device__ __forceinline__ void cp16(unsigned dst, const void* src, bool ok)
{
    int sz = ok ? 16 : 0;
    asm volatile("cp.async.cg.shared.global [%0], [%1], 16, %2;"
                 :: "r"(dst), "l"(src), "r"(sz));
}
__device__ __forceinline__ void cp_commit()
{
    asm volatile("cp.async.commit_group;");
}
__device__ __forceinline__ void cp_wait0()
{
    asm volatile("cp.async.wait_group 0;" ::: "memory");
}

// ---------------- u/w rank-1 terms: u[h,n]=<att_h, xl[n,h,:]>, w likewise ---
__global__ __launch_bounds__(128) void uw_kernel(const float* __restrict__ xl,
                                                 const float* __restrict__ xr,
                                                 const float* __restrict__ att_l,
                                                 float* __restrict__ u,
                                                 float* __restrict__ w)
{
    int n = blockIdx.x;
    int h = threadIdx.x >> 5, lane = threadIdx.x & 31;
    const float4* xlp = (const float4*)&xl[(size_t)n * HC_ + h * C_];
    const float4* xrp = (const float4*)&xr[(size_t)n * HC_ + h * C_];
    const float4* ap  = (const float4*)&att_l[h * C_];
    float su = 0.f, sw = 0.f;
#pragma unroll
    for (int i = 0; i < 2; i++) {
        float4 a = ap[lane + 32 * i];
        float4 vl = xlp[lane + 32 * i];
        float4 vr = xrp[lane + 32 * i];
        su += a.x * vl.x + a.y * vl.y + a.z * vl.z + a.w * vl.w;
        sw += a.x * vr.x + a.y * vr.y + a.z * vr.z + a.w * vr.w;
    }
#pragma unroll
    for (int o = 16; o; o >>= 1) {
        su += __shfl_xor_sync(0xffffffffu, su, o);
        sw += __shfl_xor_sync(0xffffffffu, sw, o);
    }
    if (lane == 0) {
        u[h * NN_ + n] = su;
        w[h * NN_ + n] = sw;
    }
}

// ---------------- fused logits + softmax + aggregation ----------------------
// grid (43 d-tiles, 8 bh), block 128 = 4 warps, warp = one d-row.
// cp.async double-buffered staging pipelines L2 latency behind compute.
// logit(d,s) = 0.6*(u_s + w_d) + 0.4 * sum_c att_c * |xl[s,c]+xr[d,c]|
struct AttnSmem {
    union {
        struct {
            float XLs[2][6][32][38];   // double-buffered xl tiles (stride 38: conflict-free LDS.64)
            float XR[4][256];          // all xr channels for this block's 4 d-rows (staged once)
            float A4[256];             // 0.4*att (staged once)
        } pa;
        struct {
            float Xs[2][32][260];      // double-buffered xl tiles for phase B (16B-aligned rows)
        } pb;
    } u;
    float AL[4][193];
};
#define ATTN_SMEM_BYTES sizeof(AttnSmem)

__global__ __launch_bounds__(128) void attn_agg_kernel(const float* __restrict__ xl,
                                                       const float* __restrict__ xr,
                                                       const float* __restrict__ att_l,
                                                       const float* __restrict__ u,
                                                       const float* __restrict__ w,
                                                       float* __restrict__ agg)
{
    extern __shared__ __align__(16) char smem_raw[];
    AttnSmem* sm = (AttnSmem*)smem_raw;

    int tid = threadIdx.x;
    int lane = tid & 31;
    int ty = tid >> 5;            // warp = d-row 0..3
    int dt = blockIdx.x, bh = blockIdx.y;
    int b = bh >> 2, h = bh & 3;
    int d = dt * 4 + ty;
    bool dok = d < N_;

    const float* xlh = xl + (size_t)b * N_ * HC_ + h * C_;   // row n: xlh[n*HC_ + c]

    // ---- stage chunk 0 of XLs (async), then XR + A4 (sync LDG, once) ----
#pragma unroll
    for (int i = 0; i < 24; i++) {
        int f = tid + 128 * i;          // 3072 float2
        int st = f >> 9;
        int rem = f & 511;
        int row = rem >> 4;
        int cc = (rem & 15) * 2;
        int s = st * 32 + row;
        bool ok = s < N_;
        cp8(s2u(&sm->u.pa.XLs[0][st][row][cc]),
            &xlh[(size_t)(ok ? s : 0) * HC_ + cc], ok);
    }
    cp_commit();
#pragma unroll
    for (int i = 0; i < 4; i++) {
        int f = tid + 128 * i;          // 512 float2 for XR[4][256]
        int row = f >> 7;
        int cc = (f & 127) * 2;
        int dr = dt * 4 + row;
        float2 v = make_float2(0.f, 0.f);
        if (dr < N_) v = *(const float2*)&xr[(size_t)(b * N_ + dr) * HC_ + h * C_ + cc];
        *(float2*)&sm->u.pa.XR[row][cc] = v;
    }
    {
        float2 a = *(const float2*)&att_l[h * C_ + tid * 2];
        sm->u.pa.A4[tid * 2]     = 0.4f * a.x;
        sm->u.pa.A4[tid * 2 + 1] = 0.4f * a.y;
    }

    ull acc[6];
#pragma unroll
    for (int st = 0; st < 6; st++) acc[st] = 0ull;
    const ull msk = 0x7FFFFFFF7FFFFFFFULL;

    // ---------------- Phase A: pipelined over 8 ck-chunks ----------------
#pragma unroll 1
    for (int ch = 0; ch < 8; ch++) {
        cp_wait0();
        __syncthreads();
        if (ch + 1 < 8) {
            int nb = (ch + 1) & 1;
            int ckn = (ch + 1) * 32;
#pragma unroll
            for (int i = 0; i < 24; i++) {
                int f = tid + 128 * i;
                int st = f >> 9;
                int rem = f & 511;
                int row = rem >> 4;
                int cc = (rem & 15) * 2;
                int s = st * 32 + row;
                bool ok = s < N_;
                cp8(s2u(&sm->u.pa.XLs[nb][st][row][cc]),
                    &xlh[(size_t)(ok ? s : 0) * HC_ + ckn + cc], ok);
            }
            cp_commit();
        }
        int bf = ch & 1;
        int ck = ch * 32;
#pragma unroll
        for (int c2 = 0; c2 < 16; c2++) {
            ull r  = *(const ull*)&sm->u.pa.XR[ty][ck + c2 * 2];
            ull a4 = *(const ull*)&sm->u.pa.A4[ck + c2 * 2];
#pragma unroll
            for (int j = 0; j < 6; j++) {
                ull l = *(const ull*)&sm->u.pa.XLs[bf][j][lane][c2 * 2];
                ull s, m;
                asm("add.rn.f32x2 %0, %1, %2;" : "=l"(s) : "l"(l), "l"(r));
                asm("and.b64 %0, %1, %2;"      : "=l"(m) : "l"(s), "l"(msk));
                asm("fma.rn.f32x2 %0, %1, %2, %0;" : "+l"(acc[j]) : "l"(m), "l"(a4));
            }
        }
        __syncthreads();   // all warps done with buf bf before it is overwritten
    }

    // ---- prefetch phase-B chunk 0 now; softmax hides its latency ----
#pragma unroll
    for (int i = 0; i < 16; i++) {
        int f = tid + 128 * i;          // 2048 float4
        int row = f >> 6, col4 = f & 63;
        int s = row;                    // sk = 0
        bool ok = s < N_;
        cp16(s2u(&sm->u.pb.Xs[0][row][col4 * 4]),
             &xlh[(size_t)(ok ? s : 0) * HC_ + col4 * 4], ok);
    }
    cp_commit();

    // ---------------- softmax over s (one warp per d-row) ----------------
    float w_d = dok ? w[h * NN_ + b * N_ + d] : 0.f;
    float lg[6];
    float mx = -1e30f;
#pragma unroll
    for (int j = 0; j < 6; j++) {
        ull a = acc[j];
        float lo = __uint_as_float((unsigned)(a & 0xffffffffu));
        float hi = __uint_as_float((unsigned)(a >> 32));
        int s = j * 32 + lane;
        float uv = (s < N_) ? u[h * NN_ + b * N_ + s] : 0.f;
        float v = 0.6f * (uv + w_d) + lo + hi;
        if (s >= N_ || s == d) v = -1e30f;
        lg[j] = v;
        mx = fmaxf(mx, v);
    }
#pragma unroll
    for (int o = 16; o; o >>= 1) mx = fmaxf(mx, __shfl_xor_sync(0xffffffffu, mx, o));
    float sum = 0.f;
#pragma unroll
    for (int j = 0; j < 6; j++) {
        float e = __expf(lg[j] - mx);
        lg[j] = e;
        sum += e;
    }
#pragma unroll
    for (int o = 16; o; o >>= 1) sum += __shfl_xor_sync(0xffffffffu, sum, o);
    float inv = 1.f / (sum + 1e-16f);
#pragma unroll
    for (int j = 0; j < 6; j++)
        sm->AL[ty][j * 32 + lane] = lg[j] * inv;   // zeros for s>=169

    // ---------------- Phase B: pipelined agg GEMM 4d x 256c x 192s --------
    float4 acc0 = make_float4(0.f, 0.f, 0.f, 0.f);
    float4 acc1 = make_float4(0.f, 0.f, 0.f, 0.f);
#pragma unroll 1
    for (int ch = 0; ch < 6; ch++) {
        cp_wait0();
        __syncthreads();
        if (ch + 1 < 6) {
            int nb = (ch + 1) & 1;
            int skn = (ch + 1) * 32;
#pragma unroll
            for (int i = 0; i < 16; i++) {
                int f = tid + 128 * i;
                int row = f >> 6, col4 = f & 63;
                int s = skn + row;
                bool ok = s < N_;
                cp16(s2u(&sm->u.pb.Xs[nb][row][col4 * 4]),
                     &xlh[(size_t)(ok ? s : 0) * HC_ + col4 * 4], ok);
            }
            cp_commit();
        }
        int bf = ch & 1;
        int sk = ch * 32;
#pragma unroll
        for (int k = 0; k < 32; k++) {
            float av = sm->AL[ty][sk + k];
            float4 x0 = *(const float4*)&sm->u.pb.Xs[bf][k][lane * 4];
            float4 x1 = *(const float4*)&sm->u.pb.Xs[bf][k][lane * 4 + 128];
            acc0.x = fmaf(av, x0.x, acc0.x); acc0.y = fmaf(av, x0.y, acc0.y);
            acc0.z = fmaf(av, x0.z, acc0.z); acc0.w = fmaf(av, x0.w, acc0.w);
            acc1.x = fmaf(av, x1.x, acc1.x); acc1.y = fmaf(av, x1.y, acc1.y);
            acc1.z = fmaf(av, x1.z, acc1.z); acc1.w = fmaf(av, x1.w, acc1.w);
        }
        __syncthreads();
    }

    if (dok) {
        float* o = agg + ((size_t)bh * N_ + d) * C_;
        *(float4*)&o[lane * 4]       = acc0;
        *(float4*)&o[lane * 4 + 128] = acc1;
    }
}

// ---------------- fused xl/xr GEMM: 64x32 tile, kk=32, 4x2 per thread -------
__global__ __launch_bounds__(256) void gemm_dual(const float* __restrict__ A,
                                                 const float* __restrict__ B1,
                                                 const float* __restrict__ c1,
                                                 float* __restrict__ o1,
                                                 const float* __restrict__ B2,
                                                 const float* __restrict__ c2p,
                                                 float* __restrict__ o2,
                                                 int M, int K)
{
    __shared__ __align__(16) float As[32][68];
    __shared__ __align__(16) float Bs[32][33];

    const float* Bm;
    const float* bias;
    float* out;
    int n0;
    if (blockIdx.x < 32) { Bm = B1; bias = c1;  out = o1; n0 = blockIdx.x * 32; }
    else                 { Bm = B2; bias = c2p; out = o2; n0 = (blockIdx.x - 32) * 32; }

    int tid = threadIdx.x;
    int tx = tid & 15, ty = tid >> 4;
    int m0 = blockIdx.y * 64;
    int lm = tid & 63, kq = tid >> 6;
    int br = tid >> 3, bc = (tid & 7) * 4;

    float acc[4][2];
#pragma unroll
    for (int i = 0; i < 4; i++) { acc[i][0] = 0.f; acc[i][1] = 0.f; }

    for (int kk = 0; kk < K; kk += 32) {
#pragma unroll
        for (int q = 0; q < 2; q++) {
            int kb = (kq + q * 4) * 4;
            float4 f = make_float4(0.f, 0.f, 0.f, 0.f);
            if (m0 + lm < M) f = *(const float4*)&A[(size_t)(m0 + lm) * K + kk + kb];
            As[kb + 0][lm] = f.x;
            As[kb + 1][lm] = f.y;
            As[kb + 2][lm] = f.z;
            As[kb + 3][lm] = f.w;
        }
        {
            float4 f = *(const float4*)&Bm[(size_t)(kk + br) * HC_ + n0 + bc];
            Bs[br][bc + 0] = f.x;
            Bs[br][bc + 1] = f.y;
            Bs[br][bc + 2] = f.z;
            Bs[br][bc + 3] = f.w;
        }
        __syncthreads();
#pragma unroll
        for (int k = 0; k < 32; k++) {
            float4 a = *(const float4*)&As[k][ty * 4];
            float bv0 = Bs[k][tx * 2], bv1 = Bs[k][tx * 2 + 1];
            acc[0][0] = fmaf(a.x, bv0, acc[0][0]); acc[0][1] = fmaf(a.x, bv1, acc[0][1]);
            acc[1][0] = fmaf(a.y, bv0, acc[1][0]); acc[1][1] = fmaf(a.y, bv1, acc[1][1]);
            acc[2][0] = fmaf(a.z, bv0, acc[2][0]); acc[2][1] = fmaf(a.z, bv1, acc[2][1]);
            acc[3][0] = fmaf(a.w, bv0, acc[3][0]); acc[3][1] = fmaf(a.w, bv1, acc[3][1]);
        }
        __syncthreads();
    }

    float b0 = bias[n0 + tx * 2], b1 = bias[n0 + tx * 2 + 1];
#pragma unroll
    for (int i = 0; i < 4; i++) {
        int r = m0 + ty * 4 + i;
        if (r < M) {
            out[(size_t)r * HC_ + n0 + tx * 2]     = acc[i][0] + b0;
            out[(size_t)r * HC_ + n0 + tx * 2 + 1] = acc[i][1] + b1;
        }
    }
}

// ---------------- generic 32x32 tiled fp32 GEMM (MLP path) ------------------
// mode: 1 relu, 2 residual +=
__global__ void gemm_kernel(const float* __restrict__ A,
                            const float* __restrict__ Bm,
                            const float* __restrict__ bias,
                            float* __restrict__ out,
                            int M, int N, int K, int mode)
{
    __shared__ float As[32][33];
    __shared__ float Bs[32][33];
    int tid = threadIdx.x;
    int tx = tid & 15, ty = tid >> 4;
    int m0 = blockIdx.y * 32;
    int n0 = blockIdx.x * 32;
    int lr = tid >> 3, lc = (tid & 7) * 4;
    float a00 = 0.f, a01 = 0.f, a10 = 0.f, a11 = 0.f;

    for (int kk = 0; kk < K; kk += 32) {
        {
            float4 f = make_float4(0.f, 0.f, 0.f, 0.f);
            if (m0 + lr < M) f = *(const float4*)&A[(size_t)(m0 + lr) * K + kk + lc];
            As[lr][lc + 0] = f.x; As[lr][lc + 1] = f.y;
            As[lr][lc + 2] = f.z; As[lr][lc + 3] = f.w;
            float4 g = *(const float4*)&Bm[(size_t)(kk + lr) * N + n0 + lc];
            Bs[lr][lc + 0] = g.x; Bs[lr][lc + 1] = g.y;
            Bs[lr][lc + 2] = g.z; Bs[lr][lc + 3] = g.w;
        }
        __syncthreads();
#pragma unroll
        for (int k = 0; k < 32; k++) {
            float av0 = As[ty][k],      av1 = As[ty + 16][k];
            float bv0 = Bs[k][tx],      bv1 = Bs[k][tx + 16];
            a00 = fmaf(av0, bv0, a00);  a01 = fmaf(av0, bv1, a01);
            a10 = fmaf(av1, bv0, a10);  a11 = fmaf(av1, bv1, a11);
        }
        __syncthreads();
    }

    int r0 = m0 + ty, r1 = m0 + ty + 16;
    int c0 = n0 + tx, c1 = n0 + tx + 16;
    float b0 = bias[c0], b1 = bias[c1];
    if (mode == 1) {
        if (r0 < M) { out[r0 * N + c0] = fmaxf(a00 + b0, 0.f); out[r0 * N + c1] = fmaxf(a01 + b1, 0.f); }
        if (r1 < M) { out[r1 * N + c0] = fmaxf(a10 + b0, 0.f); out[r1 * N + c1] = fmaxf(a11 + b1, 0.f); }
    } else {
        if (r0 < M) { out[r0 * N + c0] += a00 + b0; out[r0 * N + c1] += a01 + b1; }
        if (r1 < M) { out[r1 * N + c0] += a10 + b0; out[r1 * N + c1] += a11 + b1; }
    }
}

// ---------------- head-mean + bias + layernorm (4 rows/block, float4) -------
__global__ __launch_bounds__(256) void ln_kernel(const float* __restrict__ agg,
                                                 const float* __restrict__ bias_l,
                                                 const float* __restrict__ g,
                                                 const float* __restrict__ bt,
                                                 float* __restrict__ out)
{
    int ty = threadIdx.x >> 6;
    int tx = threadIdx.x & 63;
    int wq = threadIdx.x >> 5;
    int n = blockIdx.x * 4 + ty;
    bool ok = n < NN_;
    int b = (n >= N_) ? 1 : 0;
    int d = n - b * N_;

    float4 v = make_float4(0.f, 0.f, 0.f, 0.f);
    if (ok) {
#pragma unroll
        for (int h = 0; h < H_; h++) {
            float4 t = *(const float4*)&agg[((size_t)(b * H_ + h) * N_ + d) * C_ + tx * 4];
            v.x += t.x; v.y += t.y; v.z += t.z; v.w += t.w;
        }
        float4 bb = *(const float4*)&bias_l[tx * 4];
        v.x = 0.25f * v.x + bb.x; v.y = 0.25f * v.y + bb.y;
        v.z = 0.25f * v.z + bb.z; v.w = 0.25f * v.w + bb.w;
    }

    __shared__ float red[8];
    float s = v.x + v.y + v.z + v.w;
#pragma unroll
    for (int o = 16; o; o >>= 1) s += __shfl_xor_sync(0xffffffffu, s, o);
    if ((threadIdx.x & 31) == 0) red[wq] = s;
    __syncthreads();
    float mu = (red[ty * 2] + red[ty * 2 + 1]) * (1.f / C_);
    __syncthreads();

    float4 dd = make_float4(v.x - mu, v.y - mu, v.z - mu, v.w - mu);
    float s2 = dd.x * dd.x + dd.y * dd.y + dd.z * dd.z + dd.w * dd.w;
#pragma unroll
    for (int o = 16; o; o >>= 1) s2 += __shfl_xor_sync(0xffffffffu, s2, o);
    if ((threadIdx.x & 31) == 0) red[wq] = s2;
    __syncthreads();
    float rstd = rsqrtf((red[ty * 2] + red[ty * 2 + 1]) * (1.f / C_) + 1e-5f);

    if (ok) {
        float4 gg = *(const float4*)&g[tx * 4];
        float4 tb = *(const float4*)&bt[tx * 4];
        float4 o4;
        o4.x = dd.x * rstd * gg.x + tb.x;
        o4.y = dd.y * rstd * gg.y + tb.y;
        o4.z = dd.z * rstd * gg.z + tb.z;
        o4.w = dd.w * rstd * gg.w + tb.w;
        *(float4*)&out[(size_t)n * C_ + tx * 4] = o4;
    }
}

// ---------------- final mean pool per graph ----------------------------------
__global__ void pool_kernel(const float* __restrict__ x, float* __restrict__ out)
{
    int b = blockIdx.x, t = threadIdx.x;
    float s = 0.f;
#pragma unroll 13
    for (int d = 0; d < N_; d++) s += x[(b * N_ + d) * C_ + t];
    out[b * C_ + t] = s * (1.f / N_);
}

__global__ void copy_kernel(const float* __restrict__ src, float* __restrict__ dst)
{
    int i = blockIdx.x * 256 + threadIdx.x;
    dst[i] = src[i];
}

// ---------------- host launcher -----------------------------------------------
extern "C" void kernel_launch(void* const* d_in, const int* in_sizes, int n_in,
                              void* d_out, int out_size)
{
    const float* x    = (const float*)d_in[0];
    const float* Wl   = (const float*)d_in[1];
    const float* bl   = (const float*)d_in[2];
    const float* Wr   = (const float*)d_in[3];
    const float* br   = (const float*)d_in[4];
    const float* att  = (const float*)d_in[5];
    const float* bias = (const float*)d_in[6];
    const float* lng  = (const float*)d_in[7];
    const float* lnb  = (const float*)d_in[8];
    const float* W1   = (const float*)d_in[9];
    const float* b1   = (const float*)d_in[10];
    const float* W2   = (const float*)d_in[11];
    const float* b2   = (const float*)d_in[12];

    float *bx, *bxl, *bxr, *bag, *bh, *bm, *bu, *bw;
    cudaGetSymbolAddress((void**)&bx,  g_x);
    cudaGetSymbolAddress((void**)&bxl, g_xl);
    cudaGetSymbolAddress((void**)&bxr, g_xr);
    cudaGetSymbolAddress((void**)&bag, g_agg);
    cudaGetSymbolAddress((void**)&bh,  g_h);
    cudaGetSymbolAddress((void**)&bm,  g_m);
    cudaGetSymbolAddress((void**)&bu,  g_u);
    cudaGetSymbolAddress((void**)&bw,  g_w);

    static int attr_done = 0;
    if (!attr_done) {
        cudaFuncSetAttribute(attn_agg_kernel,
                             cudaFuncAttributeMaxDynamicSharedMemorySize,
                             (int)ATTN_SMEM_BYTES);
        attr_done = 1;
    }

    copy_kernel<<<NN_, 256>>>(x, bx);

    for (int l = 0; l < L_; l++) {
        gemm_dual<<<dim3(64, 6), 256>>>(bx,
                                        Wl + l * C_ * HC_, bl + l * HC_, bxl,
                                        Wr + l * C_ * HC_, br + l * HC_, bxr,
                                        NN_, C_);
        uw_kernel<<<NN_, 128>>>(bxl, bxr, att + l * H_ * C_, bu, bw);
        attn_agg_kernel<<<dim3(43, 8), 128, ATTN_SMEM_BYTES>>>(
            bxl, bxr, att + l * H_ * C_, bu, bw, bag);
        ln_kernel<<<85, 256>>>(bag, bias + l * C_, lng + l * C_, lnb + l * C_, bh);
        gemm_kernel<<<dim3(16, 11), 256>>>(bh, W1 + l * C_ * 2 * C_, b1 + l * 2 * C_,
                                           bm, NN_, 2 * C_, C_, 1);
        gemm_kernel<<<dim3(8, 11), 256>>>(bm, W2 + l * 2 * C_ * C_, b2 + l * C_,
                                          bx, NN_, C_, 2 * C_, 2);
    }

    pool_kernel<<<B_, 256>>>(bx, (float*)d_out);
}

// round 9
// speedup vs baseline: 1.3867x; 1.2191x over previous
#include <cuda_runtime.h>

#define B_   2
#define N_   169
#define NN_  338
#define C_   256
#define H_   4
#define HC_  1024
#define L_   3

typedef unsigned long long ull;

// ---------------- scratch (device globals) ---------------------------------
__device__ float g_x[NN_ * C_];               // running node features
__device__ float g_xl[NN_ * HC_];             // x @ Wl + bl
__device__ float g_xr[NN_ * HC_];             // x @ Wr + br
__device__ float g_agg[B_ * H_ * N_ * C_];    // per-head aggregation partials
__device__ float g_h[NN_ * C_];               // post layernorm
__device__ float g_m[NN_ * 2 * C_];           // mlp hidden
__device__ float g_u[H_ * NN_];               // <att, xl_n> per head
__device__ float g_w[H_ * NN_];               // <att, xr_n> per head

// ---------------- cp.async helpers ------------------------------------------
__device__ __forceinline__ unsigned s2u(const void* p)
{
    return (unsigned)__cvta_generic_to_shared(p);
}
__device__ __forceinline__ void cp8(unsigned dst, const void* src, bool ok)
{
    int sz = ok ? 8 : 0;
    asm volatile("cp.async.ca.shared.global [%0], [%1], 8, %2;"
                 :: "r"(dst), "l"(src), "r"(sz));
}
__device__ __forceinline__ void cp16(unsigned dst, const void* src, bool ok)
{
    int sz = ok ? 16 : 0;
    asm volatile("cp.async.cg.shared.global [%0], [%1], 16, %2;"
                 :: "r"(dst), "l"(src), "r"(sz));
}
__device__ __forceinline__ void cp_commit()
{
    asm volatile("cp.async.commit_group;");
}
__device__ __forceinline__ void cp_wait0()
{
    asm volatile("cp.async.wait_group 0;" ::: "memory");
}

// ---------------- u/w rank-1 terms: u[h,n]=<att_h, xl[n,h,:]>, w likewise ---
__global__ __launch_bounds__(128) void uw_kernel(const float* __restrict__ xl,
                                                 const float* __restrict__ xr,
                                                 const float* __restrict__ att_l,
                                                 float* __restrict__ u,
                                                 float* __restrict__ w)
{
    int n = blockIdx.x;
    int h = threadIdx.x >> 5, lane = threadIdx.x & 31;
    const float4* xlp = (const float4*)&xl[(size_t)n * HC_ + h * C_];
    const float4* xrp = (const float4*)&xr[(size_t)n * HC_ + h * C_];
    const float4* ap  = (const float4*)&att_l[h * C_];
    float su = 0.f, sw = 0.f;
#pragma unroll
    for (int i = 0; i < 2; i++) {
        float4 a = ap[lane + 32 * i];
        float4 vl = xlp[lane + 32 * i];
        float4 vr = xrp[lane + 32 * i];
        su += a.x * vl.x + a.y * vl.y + a.z * vl.z + a.w * vl.w;
        sw += a.x * vr.x + a.y * vr.y + a.z * vr.z + a.w * vr.w;
    }
#pragma unroll
    for (int o = 16; o; o >>= 1) {
        su += __shfl_xor_sync(0xffffffffu, su, o);
        sw += __shfl_xor_sync(0xffffffffu, sw, o);
    }
    if (lane == 0) {
        u[h * NN_ + n] = su;
        w[h * NN_ + n] = sw;
    }
}

// ---------------- fused logits + softmax + aggregation ----------------------
// grid (43 d-tiles, 8 bh), block 128 = 4 warps, warp = one d-row.
// cp.async double-buffered staging pipelines L2 latency behind compute.
struct AttnSmem {
    union {
        struct {
            float XLs[2][6][32][38];
            float XR[4][256];
            float A4[256];
        } pa;
        struct {
            float Xs[2][32][260];
        } pb;
    } u;
    float AL[4][193];
};
#define ATTN_SMEM_BYTES sizeof(AttnSmem)

__global__ __launch_bounds__(128) void attn_agg_kernel(const float* __restrict__ xl,
                                                       const float* __restrict__ xr,
                                                       const float* __restrict__ att_l,
                                                       const float* __restrict__ u,
                                                       const float* __restrict__ w,
                                                       float* __restrict__ agg)
{
    extern __shared__ __align__(16) char smem_raw[];
    AttnSmem* sm = (AttnSmem*)smem_raw;

    int tid = threadIdx.x;
    int lane = tid & 31;
    int ty = tid >> 5;
    int dt = blockIdx.x, bh = blockIdx.y;
    int b = bh >> 2, h = bh & 3;
    int d = dt * 4 + ty;
    bool dok = d < N_;

    const float* xlh = xl + (size_t)b * N_ * HC_ + h * C_;

#pragma unroll
    for (int i = 0; i < 24; i++) {
        int f = tid + 128 * i;
        int st = f >> 9;
        int rem = f & 511;
        int row = rem >> 4;
        int cc = (rem & 15) * 2;
        int s = st * 32 + row;
        bool ok = s < N_;
        cp8(s2u(&sm->u.pa.XLs[0][st][row][cc]),
            &xlh[(size_t)(ok ? s : 0) * HC_ + cc], ok);
    }
    cp_commit();
#pragma unroll
    for (int i = 0; i < 4; i++) {
        int f = tid + 128 * i;
        int row = f >> 7;
        int cc = (f & 127) * 2;
        int dr = dt * 4 + row;
        float2 v = make_float2(0.f, 0.f);
        if (dr < N_) v = *(const float2*)&xr[(size_t)(b * N_ + dr) * HC_ + h * C_ + cc];
        *(float2*)&sm->u.pa.XR[row][cc] = v;
    }
    {
        float2 a = *(const float2*)&att_l[h * C_ + tid * 2];
        sm->u.pa.A4[tid * 2]     = 0.4f * a.x;
        sm->u.pa.A4[tid * 2 + 1] = 0.4f * a.y;
    }

    ull acc[6];
#pragma unroll
    for (int st = 0; st < 6; st++) acc[st] = 0ull;
    const ull msk = 0x7FFFFFFF7FFFFFFFULL;

#pragma unroll 1
    for (int ch = 0; ch < 8; ch++) {
        cp_wait0();
        __syncthreads();
        if (ch + 1 < 8) {
            int nb = (ch + 1) & 1;
            int ckn = (ch + 1) * 32;
#pragma unroll
            for (int i = 0; i < 24; i++) {
                int f = tid + 128 * i;
                int st = f >> 9;
                int rem = f & 511;
                int row = rem >> 4;
                int cc = (rem & 15) * 2;
                int s = st * 32 + row;
                bool ok = s < N_;
                cp8(s2u(&sm->u.pa.XLs[nb][st][row][cc]),
                    &xlh[(size_t)(ok ? s : 0) * HC_ + ckn + cc], ok);
            }
            cp_commit();
        }
        int bf = ch & 1;
        int ck = ch * 32;
#pragma unroll
        for (int c2 = 0; c2 < 16; c2++) {
            ull r  = *(const ull*)&sm->u.pa.XR[ty][ck + c2 * 2];
            ull a4 = *(const ull*)&sm->u.pa.A4[ck + c2 * 2];
#pragma unroll
            for (int j = 0; j < 6; j++) {
                ull l = *(const ull*)&sm->u.pa.XLs[bf][j][lane][c2 * 2];
                ull s, m;
                asm("add.rn.f32x2 %0, %1, %2;" : "=l"(s) : "l"(l), "l"(r));
                asm("and.b64 %0, %1, %2;"      : "=l"(m) : "l"(s), "l"(msk));
                asm("fma.rn.f32x2 %0, %1, %2, %0;" : "+l"(acc[j]) : "l"(m), "l"(a4));
            }
        }
        __syncthreads();
    }

#pragma unroll
    for (int i = 0; i < 16; i++) {
        int f = tid + 128 * i;
        int row = f >> 6, col4 = f & 63;
        int s = row;
        bool ok = s < N_;
        cp16(s2u(&sm->u.pb.Xs[0][row][col4 * 4]),
             &xlh[(size_t)(ok ? s : 0) * HC_ + col4 * 4], ok);
    }
    cp_commit();

    float w_d = dok ? w[h * NN_ + b * N_ + d] : 0.f;
    float lg[6];
    float mx = -1e30f;
#pragma unroll
    for (int j = 0; j < 6; j++) {
        ull a = acc[j];
        float lo = __uint_as_float((unsigned)(a & 0xffffffffu));
        float hi = __uint_as_float((unsigned)(a >> 32));
        int s = j * 32 + lane;
        float uv = (s < N_) ? u[h * NN_ + b * N_ + s] : 0.f;
        float v = 0.6f * (uv + w_d) + lo + hi;
        if (s >= N_ || s == d) v = -1e30f;
        lg[j] = v;
        mx = fmaxf(mx, v);
    }
#pragma unroll
    for (int o = 16; o; o >>= 1) mx = fmaxf(mx, __shfl_xor_sync(0xffffffffu, mx, o));
    float sum = 0.f;
#pragma unroll
    for (int j = 0; j < 6; j++) {
        float e = __expf(lg[j] - mx);
        lg[j] = e;
        sum += e;
    }
#pragma unroll
    for (int o = 16; o; o >>= 1) sum += __shfl_xor_sync(0xffffffffu, sum, o);
    float inv = 1.f / (sum + 1e-16f);
#pragma unroll
    for (int j = 0; j < 6; j++)
        sm->AL[ty][j * 32 + lane] = lg[j] * inv;

    float4 acc0 = make_float4(0.f, 0.f, 0.f, 0.f);
    float4 acc1 = make_float4(0.f, 0.f, 0.f, 0.f);
#pragma unroll 1
    for (int ch = 0; ch < 6; ch++) {
        cp_wait0();
        __syncthreads();
        if (ch + 1 < 6) {
            int nb = (ch + 1) & 1;
            int skn = (ch + 1) * 32;
#pragma unroll
            for (int i = 0; i < 16; i++) {
                int f = tid + 128 * i;
                int row = f >> 6, col4 = f & 63;
                int s = skn + row;
                bool ok = s < N_;
                cp16(s2u(&sm->u.pb.Xs[nb][row][col4 * 4]),
                     &xlh[(size_t)(ok ? s : 0) * HC_ + col4 * 4], ok);
            }
            cp_commit();
        }
        int bf = ch & 1;
        int sk = ch * 32;
#pragma unroll
        for (int k = 0; k < 32; k++) {
            float av = sm->AL[ty][sk + k];
            float4 x0 = *(const float4*)&sm->u.pb.Xs[bf][k][lane * 4];
            float4 x1 = *(const float4*)&sm->u.pb.Xs[bf][k][lane * 4 + 128];
            acc0.x = fmaf(av, x0.x, acc0.x); acc0.y = fmaf(av, x0.y, acc0.y);
            acc0.z = fmaf(av, x0.z, acc0.z); acc0.w = fmaf(av, x0.w, acc0.w);
            acc1.x = fmaf(av, x1.x, acc1.x); acc1.y = fmaf(av, x1.y, acc1.y);
            acc1.z = fmaf(av, x1.z, acc1.z); acc1.w = fmaf(av, x1.w, acc1.w);
        }
        __syncthreads();
    }

    if (dok) {
        float* o = agg + ((size_t)bh * N_ + d) * C_;
        *(float4*)&o[lane * 4]       = acc0;
        *(float4*)&o[lane * 4 + 128] = acc1;
    }
}

// ---------------- fused xl/xr GEMM, cp.async double-buffered ----------------
// 64x32 tile, kk=32, 4x2 per thread. A staged row-major [64][36].
__global__ __launch_bounds__(256) void gemm_dual(const float* __restrict__ A,
                                                 const float* __restrict__ B1,
                                                 const float* __restrict__ c1,
                                                 float* __restrict__ o1,
                                                 const float* __restrict__ B2,
                                                 const float* __restrict__ c2p,
                                                 float* __restrict__ o2,
                                                 int M, int K)
{
    __shared__ __align__(16) float As[2][64][36];
    __shared__ __align__(16) float Bs[2][32][36];

    const float* Bm;
    const float* bias;
    float* out;
    int n0;
    if (blockIdx.x < 32) { Bm = B1; bias = c1;  out = o1; n0 = blockIdx.x * 32; }
    else                 { Bm = B2; bias = c2p; out = o2; n0 = (blockIdx.x - 32) * 32; }

    int tid = threadIdx.x;
    int tx = tid & 15, ty = tid >> 4;
    int m0 = blockIdx.y * 64;

    // staging maps
    int a_row = tid >> 2, a_c4a = (tid & 3) * 2;      // 2 float4 per thread (c4, c4+1)
    int b_row = tid >> 3, b_c4 = tid & 7;             // 1 float4 per thread

    // prologue: stage chunk 0
    {
        bool okA = (m0 + a_row) < M;
        const float* srcA = &A[(size_t)(m0 + (okA ? a_row : 0)) * K + a_c4a * 4];
        cp16(s2u(&As[0][a_row][a_c4a * 4]), srcA, okA);
        cp16(s2u(&As[0][a_row][(a_c4a + 1) * 4]), srcA + 4, okA);
        cp16(s2u(&Bs[0][b_row][b_c4 * 4]),
             &Bm[(size_t)b_row * HC_ + n0 + b_c4 * 4], true);
    }
    cp_commit();

    float acc[4][2];
#pragma unroll
    for (int i = 0; i < 4; i++) { acc[i][0] = 0.f; acc[i][1] = 0.f; }

    int nch = K / 32;
#pragma unroll 1
    for (int ch = 0; ch < nch; ch++) {
        cp_wait0();
        __syncthreads();
        if (ch + 1 < nch) {
            int nb = (ch + 1) & 1;
            int kkn = (ch + 1) * 32;
            bool okA = (m0 + a_row) < M;
            const float* srcA = &A[(size_t)(m0 + (okA ? a_row : 0)) * K + kkn + a_c4a * 4];
            cp16(s2u(&As[nb][a_row][a_c4a * 4]), srcA, okA);
            cp16(s2u(&As[nb][a_row][(a_c4a + 1) * 4]), srcA + 4, okA);
            cp16(s2u(&Bs[nb][b_row][b_c4 * 4]),
                 &Bm[(size_t)(kkn + b_row) * HC_ + n0 + b_c4 * 4], true);
            cp_commit();
        }
        int bf = ch & 1;
#pragma unroll
        for (int k = 0; k < 32; k++) {
            float a0 = As[bf][ty * 4 + 0][k];
            float a1 = As[bf][ty * 4 + 1][k];
            float a2 = As[bf][ty * 4 + 2][k];
            float a3 = As[bf][ty * 4 + 3][k];
            float2 bv = *(const float2*)&Bs[bf][k][tx * 2];
            acc[0][0] = fmaf(a0, bv.x, acc[0][0]); acc[0][1] = fmaf(a0, bv.y, acc[0][1]);
            acc[1][0] = fmaf(a1, bv.x, acc[1][0]); acc[1][1] = fmaf(a1, bv.y, acc[1][1]);
            acc[2][0] = fmaf(a2, bv.x, acc[2][0]); acc[2][1] = fmaf(a2, bv.y, acc[2][1]);
            acc[3][0] = fmaf(a3, bv.x, acc[3][0]); acc[3][1] = fmaf(a3, bv.y, acc[3][1]);
        }
        __syncthreads();
    }

    float b0 = bias[n0 + tx * 2], b1 = bias[n0 + tx * 2 + 1];
#pragma unroll
    for (int i = 0; i < 4; i++) {
        int r = m0 + ty * 4 + i;
        if (r < M) {
            out[(size_t)r * HC_ + n0 + tx * 2]     = acc[i][0] + b0;
            out[(size_t)r * HC_ + n0 + tx * 2 + 1] = acc[i][1] + b1;
        }
    }
}

// ---------------- generic 32x32 GEMM, cp.async double-buffered --------------
// mode: 1 relu, 2 residual +=
__global__ void gemm_kernel(const float* __restrict__ A,
                            const float* __restrict__ Bm,
                            const float* __restrict__ bias,
                            float* __restrict__ out,
                            int M, int N, int K, int mode)
{
    __shared__ __align__(16) float As[2][32][36];
    __shared__ __align__(16) float Bs[2][32][36];
    int tid = threadIdx.x;
    int tx = tid & 15, ty = tid >> 4;
    int m0 = blockIdx.y * 32;
    int n0 = blockIdx.x * 32;
    int lr = tid >> 3, lc4 = tid & 7;
    float a00 = 0.f, a01 = 0.f, a10 = 0.f, a11 = 0.f;

    {
        bool okA = (m0 + lr) < M;
        cp16(s2u(&As[0][lr][lc4 * 4]),
             &A[(size_t)(m0 + (okA ? lr : 0)) * K + lc4 * 4], okA);
        cp16(s2u(&Bs[0][lr][lc4 * 4]),
             &Bm[(size_t)lr * N + n0 + lc4 * 4], true);
    }
    cp_commit();

    int nch = K / 32;
#pragma unroll 1
    for (int ch = 0; ch < nch; ch++) {
        cp_wait0();
        __syncthreads();
        if (ch + 1 < nch) {
            int nb = (ch + 1) & 1;
            int kkn = (ch + 1) * 32;
            bool okA = (m0 + lr) < M;
            cp16(s2u(&As[nb][lr][lc4 * 4]),
                 &A[(size_t)(m0 + (okA ? lr : 0)) * K + kkn + lc4 * 4], okA);
            cp16(s2u(&Bs[nb][lr][lc4 * 4]),
                 &Bm[(size_t)(kkn + lr) * N + n0 + lc4 * 4], true);
            cp_commit();
        }
        int bf = ch & 1;
#pragma unroll
        for (int k = 0; k < 32; k++) {
            float av0 = As[bf][ty][k],      av1 = As[bf][ty + 16][k];
            float bv0 = Bs[bf][k][tx],      bv1 = Bs[bf][k][tx + 16];
            a00 = fmaf(av0, bv0, a00);  a01 = fmaf(av0, bv1, a01);
            a10 = fmaf(av1, bv0, a10);  a11 = fmaf(av1, bv1, a11);
        }
        __syncthreads();
    }

    int r0 = m0 + ty, r1 = m0 + ty + 16;
    int c0 = n0 + tx, c1 = n0 + tx + 16;
    float b0 = bias[c0], b1 = bias[c1];
    if (mode == 1) {
        if (r0 < M) { out[r0 * N + c0] = fmaxf(a00 + b0, 0.f); out[r0 * N + c1] = fmaxf(a01 + b1, 0.f); }
        if (r1 < M) { out[r1 * N + c0] = fmaxf(a10 + b0, 0.f); out[r1 * N + c1] = fmaxf(a11 + b1, 0.f); }
    } else {
        if (r0 < M) { out[r0 * N + c0] += a00 + b0; out[r0 * N + c1] += a01 + b1; }
        if (r1 < M) { out[r1 * N + c0] += a10 + b0; out[r1 * N + c1] += a11 + b1; }
    }
}

// ---------------- head-mean + bias + layernorm (4 rows/block, float4) -------
__global__ __launch_bounds__(256) void ln_kernel(const float* __restrict__ agg,
                                                 const float* __restrict__ bias_l,
                                                 const float* __restrict__ g,
                                                 const float* __restrict__ bt,
                                                 float* __restrict__ out)
{
    int ty = threadIdx.x >> 6;
    int tx = threadIdx.x & 63;
    int wq = threadIdx.x >> 5;
    int n = blockIdx.x * 4 + ty;
    bool ok = n < NN_;
    int b = (n >= N_) ? 1 : 0;
    int d = n - b * N_;

    float4 v = make_float4(0.f, 0.f, 0.f, 0.f);
    if (ok) {
#pragma unroll
        for (int h = 0; h < H_; h++) {
            float4 t = *(const float4*)&agg[((size_t)(b * H_ + h) * N_ + d) * C_ + tx * 4];
            v.x += t.x; v.y += t.y; v.z += t.z; v.w += t.w;
        }
        float4 bb = *(const float4*)&bias_l[tx * 4];
        v.x = 0.25f * v.x + bb.x; v.y = 0.25f * v.y + bb.y;
        v.z = 0.25f * v.z + bb.z; v.w = 0.25f * v.w + bb.w;
    }

    __shared__ float red[8];
    float s = v.x + v.y + v.z + v.w;
#pragma unroll
    for (int o = 16; o; o >>= 1) s += __shfl_xor_sync(0xffffffffu, s, o);
    if ((threadIdx.x & 31) == 0) red[wq] = s;
    __syncthreads();
    float mu = (red[ty * 2] + red[ty * 2 + 1]) * (1.f / C_);
    __syncthreads();

    float4 dd = make_float4(v.x - mu, v.y - mu, v.z - mu, v.w - mu);
    float s2 = dd.x * dd.x + dd.y * dd.y + dd.z * dd.z + dd.w * dd.w;
#pragma unroll
    for (int o = 16; o; o >>= 1) s2 += __shfl_xor_sync(0xffffffffu, s2, o);
    if ((threadIdx.x & 31) == 0) red[wq] = s2;
    __syncthreads();
    float rstd = rsqrtf((red[ty * 2] + red[ty * 2 + 1]) * (1.f / C_) + 1e-5f);

    if (ok) {
        float4 gg = *(const float4*)&g[tx * 4];
        float4 tb = *(const float4*)&bt[tx * 4];
        float4 o4;
        o4.x = dd.x * rstd * gg.x + tb.x;
        o4.y = dd.y * rstd * gg.y + tb.y;
        o4.z = dd.z * rstd * gg.z + tb.z;
        o4.w = dd.w * rstd * gg.w + tb.w;
        *(float4*)&out[(size_t)n * C_ + tx * 4] = o4;
    }
}

// ---------------- final mean pool per graph ----------------------------------
__global__ void pool_kernel(const float* __restrict__ x, float* __restrict__ out)
{
    int b = blockIdx.x, t = threadIdx.x;
    float s = 0.f;
#pragma unroll 13
    for (int d = 0; d < N_; d++) s += x[(b * N_ + d) * C_ + t];
    out[b * C_ + t] = s * (1.f / N_);
}

__global__ void copy_kernel(const float* __restrict__ src, float* __restrict__ dst)
{
    int i = blockIdx.x * 256 + threadIdx.x;
    dst[i] = src[i];
}

// ---------------- host launcher -----------------------------------------------
extern "C" void kernel_launch(void* const* d_in, const int* in_sizes, int n_in,
                              void* d_out, int out_size)
{
    const float* x    = (const float*)d_in[0];
    const float* Wl   = (const float*)d_in[1];
    const float* bl   = (const float*)d_in[2];
    const float* Wr   = (const float*)d_in[3];
    const float* br   = (const float*)d_in[4];
    const float* att  = (const float*)d_in[5];
    const float* bias = (const float*)d_in[6];
    const float* lng  = (const float*)d_in[7];
    const float* lnb  = (const float*)d_in[8];
    const float* W1   = (const float*)d_in[9];
    const float* b1   = (const float*)d_in[10];
    const float* W2   = (const float*)d_in[11];
    const float* b2   = (const float*)d_in[12];

    float *bx, *bxl, *bxr, *bag, *bh, *bm, *bu, *bw;
    cudaGetSymbolAddress((void**)&bx,  g_x);
    cudaGetSymbolAddress((void**)&bxl, g_xl);
    cudaGetSymbolAddress((void**)&bxr, g_xr);
    cudaGetSymbolAddress((void**)&bag, g_agg);
    cudaGetSymbolAddress((void**)&bh,  g_h);
    cudaGetSymbolAddress((void**)&bm,  g_m);
    cudaGetSymbolAddress((void**)&bu,  g_u);
    cudaGetSymbolAddress((void**)&bw,  g_w);

    static int attr_done = 0;
    if (!attr_done) {
        cudaFuncSetAttribute(attn_agg_kernel,
                             cudaFuncAttributeMaxDynamicSharedMemorySize,
                             (int)ATTN_SMEM_BYTES);
        attr_done = 1;
    }

    copy_kernel<<<NN_, 256>>>(x, bx);

    for (int l = 0; l < L_; l++) {
        gemm_dual<<<dim3(64, 6), 256>>>(bx,
                                        Wl + l * C_ * HC_, bl + l * HC_, bxl,
                                        Wr + l * C_ * HC_, br + l * HC_, bxr,
                                        NN_, C_);
        uw_kernel<<<NN_, 128>>>(bxl, bxr, att + l * H_ * C_, bu, bw);
        attn_agg_kernel<<<dim3(43, 8), 128, ATTN_SMEM_BYTES>>>(
            bxl, bxr, att + l * H_ * C_, bu, bw, bag);
        ln_kernel<<<85, 256>>>(bag, bias + l * C_, lng + l * C_, lnb + l * C_, bh);
        gemm_kernel<<<dim3(16, 11), 256>>>(bh, W1 + l * C_ * 2 * C_, b1 + l * 2 * C_,
                                           bm, NN_, 2 * C_, C_, 1);
        gemm_kernel<<<dim3(8, 11), 256>>>(bm, W2 + l * 2 * C_ * C_, b2 + l * C_,
                                          bx, NN_, C_, 2 * C_, 2);
    }

    pool_kernel<<<B_, 256>>>(bx, (float*)d_out);
}

// round 10
// speedup vs baseline: 1.5119x; 1.0903x over previous
#include <cuda_runtime.h>

#define B_   2
#define N_   169
#define NN_  338
#define C_   256
#define H_   4
#define HC_  1024
#define L_   3

typedef unsigned long long ull;

// ---------------- scratch (device globals) ---------------------------------
__device__ float g_x[NN_ * C_];               // running node features
__device__ float g_xl[NN_ * HC_];             // x @ Wl + bl
__device__ float g_xr[NN_ * HC_];             // x @ Wr + br
__device__ float g_agg[B_ * H_ * N_ * C_];    // per-head aggregation partials
__device__ float g_h[NN_ * C_];               // post layernorm
__device__ float g_m[NN_ * 2 * C_];           // mlp hidden
__device__ float g_u[H_ * NN_];               // <att, xl_n> per head
__device__ float g_w[H_ * NN_];               // <att, xr_n> per head

// ---------------- cp.async helpers ------------------------------------------
__device__ __forceinline__ unsigned s2u(const void* p)
{
    return (unsigned)__cvta_generic_to_shared(p);
}
__device__ __forceinline__ void cp8(unsigned dst, const void* src, bool ok)
{
    int sz = ok ? 8 : 0;
    asm volatile("cp.async.ca.shared.global [%0], [%1], 8, %2;"
                 :: "r"(dst), "l"(src), "r"(sz));
}
__device__ __forceinline__ void cp16(unsigned dst, const void* src, bool ok)
{
    int sz = ok ? 16 : 0;
    asm volatile("cp.async.cg.shared.global [%0], [%1], 16, %2;"
                 :: "r"(dst), "l"(src), "r"(sz));
}
__device__ __forceinline__ void cp_commit()
{
    asm volatile("cp.async.commit_group;");
}
__device__ __forceinline__ void cp_wait0()
{
    asm volatile("cp.async.wait_group 0;" ::: "memory");
}

// ---------------- u/w rank-1 terms: u[h,n]=<att_h, xl[n,h,:]>, w likewise ---
__global__ __launch_bounds__(128) void uw_kernel(const float* __restrict__ xl,
                                                 const float* __restrict__ xr,
                                                 const float* __restrict__ att_l,
                                                 float* __restrict__ u,
                                                 float* __restrict__ w)
{
    int n = blockIdx.x;
    int h = threadIdx.x >> 5, lane = threadIdx.x & 31;
    const float4* xlp = (const float4*)&xl[(size_t)n * HC_ + h * C_];
    const float4* xrp = (const float4*)&xr[(size_t)n * HC_ + h * C_];
    const float4* ap  = (const float4*)&att_l[h * C_];
    float su = 0.f, sw = 0.f;
#pragma unroll
    for (int i = 0; i < 2; i++) {
        float4 a = ap[lane + 32 * i];
        float4 vl = xlp[lane + 32 * i];
        float4 vr = xrp[lane + 32 * i];
        su += a.x * vl.x + a.y * vl.y + a.z * vl.z + a.w * vl.w;
        sw += a.x * vr.x + a.y * vr.y + a.z * vr.z + a.w * vr.w;
    }
#pragma unroll
    for (int o = 16; o; o >>= 1) {
        su += __shfl_xor_sync(0xffffffffu, su, o);
        sw += __shfl_xor_sync(0xffffffffu, sw, o);
    }
    if (lane == 0) {
        u[h * NN_ + n] = su;
        w[h * NN_ + n] = sw;
    }
}

// ---------------- fused logits + softmax + aggregation ----------------------
// grid (43 d-tiles, 8 bh), block 128 = 4 warps.
// warp = (d-pair ty, s-half hf): 2 d-rows x 3 s-bands -> each XLs LDS.64
// feeds 2 d-rows (register blocking in d halves shared traffic).
struct AttnSmem {
    union {
        struct {
            float XLs[2][6][32][38];
            float XR[4][256];
            float A4[256];
        } pa;
        struct {
            float Xs[2][32][260];
        } pb;
    } u;
    float AL[4][193];
    float MX[4][2];
    float SS[4][2];
};
#define ATTN_SMEM_BYTES sizeof(AttnSmem)

__global__ __launch_bounds__(128) void attn_agg_kernel(const float* __restrict__ xl,
                                                       const float* __restrict__ xr,
                                                       const float* __restrict__ att_l,
                                                       const float* __restrict__ u,
                                                       const float* __restrict__ w,
                                                       float* __restrict__ agg)
{
    extern __shared__ __align__(16) char smem_raw[];
    AttnSmem* sm = (AttnSmem*)smem_raw;

    int tid = threadIdx.x;
    int lane = tid & 31;
    int wid = tid >> 5;
    int ty = wid >> 1;            // d-pair 0..1
    int hf = wid & 1;             // s-half: bands {0,1,2} or {3,4,5}
    int dt = blockIdx.x, bh = blockIdx.y;
    int b = bh >> 2, h = bh & 3;
    int d0 = dt * 4 + ty * 2;
    int d1 = d0 + 1;
    bool dok0 = d0 < N_, dok1 = d1 < N_;

    const float* xlh = xl + (size_t)b * N_ * HC_ + h * C_;

    // ---- stage chunk 0 of XLs (async), then XR + A4 (sync LDG, once) ----
#pragma unroll
    for (int i = 0; i < 24; i++) {
        int f = tid + 128 * i;          // 3072 float2
        int st = f >> 9;
        int rem = f & 511;
        int row = rem >> 4;
        int cc = (rem & 15) * 2;
        int s = st * 32 + row;
        bool ok = s < N_;
        cp8(s2u(&sm->u.pa.XLs[0][st][row][cc]),
            &xlh[(size_t)(ok ? s : 0) * HC_ + cc], ok);
    }
    cp_commit();
#pragma unroll
    for (int i = 0; i < 4; i++) {
        int f = tid + 128 * i;          // 512 float2 for XR[4][256]
        int row = f >> 7;
        int cc = (f & 127) * 2;
        int dr = dt * 4 + row;
        float2 v = make_float2(0.f, 0.f);
        if (dr < N_) v = *(const float2*)&xr[(size_t)(b * N_ + dr) * HC_ + h * C_ + cc];
        *(float2*)&sm->u.pa.XR[row][cc] = v;
    }
    {
        float2 a = *(const float2*)&att_l[h * C_ + tid * 2];
        sm->u.pa.A4[tid * 2]     = 0.4f * a.x;
        sm->u.pa.A4[tid * 2 + 1] = 0.4f * a.y;
    }

    ull acc0[3], acc1[3];
#pragma unroll
    for (int j = 0; j < 3; j++) { acc0[j] = 0ull; acc1[j] = 0ull; }
    const ull msk = 0x7FFFFFFF7FFFFFFFULL;

    // ---------------- Phase A: pipelined over 8 ck-chunks ----------------
#pragma unroll 1
    for (int ch = 0; ch < 8; ch++) {
        cp_wait0();
        __syncthreads();
        if (ch + 1 < 8) {
            int nb = (ch + 1) & 1;
            int ckn = (ch + 1) * 32;
#pragma unroll
            for (int i = 0; i < 24; i++) {
                int f = tid + 128 * i;
                int st = f >> 9;
                int rem = f & 511;
                int row = rem >> 4;
                int cc = (rem & 15) * 2;
                int s = st * 32 + row;
                bool ok = s < N_;
                cp8(s2u(&sm->u.pa.XLs[nb][st][row][cc]),
                    &xlh[(size_t)(ok ? s : 0) * HC_ + ckn + cc], ok);
            }
            cp_commit();
        }
        int bf = ch & 1;
        int ck = ch * 32;
#pragma unroll
        for (int c2 = 0; c2 < 16; c2++) {
            ull r0 = *(const ull*)&sm->u.pa.XR[ty * 2][ck + c2 * 2];
            ull r1 = *(const ull*)&sm->u.pa.XR[ty * 2 + 1][ck + c2 * 2];
            ull a4 = *(const ull*)&sm->u.pa.A4[ck + c2 * 2];
#pragma unroll
            for (int j = 0; j < 3; j++) {
                ull l = *(const ull*)&sm->u.pa.XLs[bf][hf * 3 + j][lane][c2 * 2];
                ull s0, m0, s1, m1;
                asm("add.rn.f32x2 %0, %1, %2;" : "=l"(s0) : "l"(l), "l"(r0));
                asm("add.rn.f32x2 %0, %1, %2;" : "=l"(s1) : "l"(l), "l"(r1));
                asm("and.b64 %0, %1, %2;"      : "=l"(m0) : "l"(s0), "l"(msk));
                asm("and.b64 %0, %1, %2;"      : "=l"(m1) : "l"(s1), "l"(msk));
                asm("fma.rn.f32x2 %0, %1, %2, %0;" : "+l"(acc0[j]) : "l"(m0), "l"(a4));
                asm("fma.rn.f32x2 %0, %1, %2, %0;" : "+l"(acc1[j]) : "l"(m1), "l"(a4));
            }
        }
        __syncthreads();
    }

    // ---- prefetch phase-B chunk 0 now; softmax hides its latency ----
#pragma unroll
    for (int i = 0; i < 16; i++) {
        int f = tid + 128 * i;          // 2048 float4
        int row = f >> 6, col4 = f & 63;
        int s = row;
        bool ok = s < N_;
        cp16(s2u(&sm->u.pb.Xs[0][row][col4 * 4]),
             &xlh[(size_t)(ok ? s : 0) * HC_ + col4 * 4], ok);
    }
    cp_commit();

    // ---------------- softmax (2 d-rows per warp, 2-warp combine) --------
    float w_d0 = dok0 ? w[h * NN_ + b * N_ + d0] : 0.f;
    float w_d1 = dok1 ? w[h * NN_ + b * N_ + d1] : 0.f;
    float lg0[3], lg1[3];
    float mx0 = -1e30f, mx1 = -1e30f;
#pragma unroll
    for (int j = 0; j < 3; j++) {
        int s = (hf * 3 + j) * 32 + lane;
        float uv = (s < N_) ? u[h * NN_ + b * N_ + s] : 0.f;
        {
            ull a = acc0[j];
            float lo = __uint_as_float((unsigned)(a & 0xffffffffu));
            float hi = __uint_as_float((unsigned)(a >> 32));
            float v = 0.6f * (uv + w_d0) + lo + hi;
            if (s >= N_ || s == d0) v = -1e30f;
            lg0[j] = v;
            mx0 = fmaxf(mx0, v);
        }
        {
            ull a = acc1[j];
            float lo = __uint_as_float((unsigned)(a & 0xffffffffu));
            float hi = __uint_as_float((unsigned)(a >> 32));
            float v = 0.6f * (uv + w_d1) + lo + hi;
            if (s >= N_ || s == d1) v = -1e30f;
            lg1[j] = v;
            mx1 = fmaxf(mx1, v);
        }
    }
#pragma unroll
    for (int o = 16; o; o >>= 1) {
        mx0 = fmaxf(mx0, __shfl_xor_sync(0xffffffffu, mx0, o));
        mx1 = fmaxf(mx1, __shfl_xor_sync(0xffffffffu, mx1, o));
    }
    if (lane == 0) {
        sm->MX[ty * 2][hf]     = mx0;
        sm->MX[ty * 2 + 1][hf] = mx1;
    }
    __syncthreads();
    float gmx0 = fmaxf(sm->MX[ty * 2][0],     sm->MX[ty * 2][1]);
    float gmx1 = fmaxf(sm->MX[ty * 2 + 1][0], sm->MX[ty * 2 + 1][1]);
    float sum0 = 0.f, sum1 = 0.f;
#pragma unroll
    for (int j = 0; j < 3; j++) {
        float e0 = __expf(lg0[j] - gmx0);
        float e1 = __expf(lg1[j] - gmx1);
        lg0[j] = e0; lg1[j] = e1;
        sum0 += e0; sum1 += e1;
    }
#pragma unroll
    for (int o = 16; o; o >>= 1) {
        sum0 += __shfl_xor_sync(0xffffffffu, sum0, o);
        sum1 += __shfl_xor_sync(0xffffffffu, sum1, o);
    }
    if (lane == 0) {
        sm->SS[ty * 2][hf]     = sum0;
        sm->SS[ty * 2 + 1][hf] = sum1;
    }
    __syncthreads();
    float inv0 = 1.f / (sm->SS[ty * 2][0]     + sm->SS[ty * 2][1]     + 1e-16f);
    float inv1 = 1.f / (sm->SS[ty * 2 + 1][0] + sm->SS[ty * 2 + 1][1] + 1e-16f);
#pragma unroll
    for (int j = 0; j < 3; j++) {
        sm->AL[ty * 2][(hf * 3 + j) * 32 + lane]     = lg0[j] * inv0;
        sm->AL[ty * 2 + 1][(hf * 3 + j) * 32 + lane] = lg1[j] * inv1;
    }
    // AL write -> read ordering provided by the __syncthreads at phase-B loop head

    // ---------------- Phase B: warp = (d-pair, c-half) -------------------
    // 2 d-rows share each Xs LDS.128.
    float4 accA = make_float4(0.f, 0.f, 0.f, 0.f);   // d0
    float4 accB = make_float4(0.f, 0.f, 0.f, 0.f);   // d1
    int cb = hf * 128 + lane * 4;
#pragma unroll 1
    for (int ch = 0; ch < 6; ch++) {
        cp_wait0();
        __syncthreads();
        if (ch + 1 < 6) {
            int nb = (ch + 1) & 1;
            int skn = (ch + 1) * 32;
#pragma unroll
            for (int i = 0; i < 16; i++) {
                int f = tid + 128 * i;
                int row = f >> 6, col4 = f & 63;
                int s = skn + row;
                bool ok = s < N_;
                cp16(s2u(&sm->u.pb.Xs[nb][row][col4 * 4]),
                     &xlh[(size_t)(ok ? s : 0) * HC_ + col4 * 4], ok);
            }
            cp_commit();
        }
        int bf = ch & 1;
        int sk = ch * 32;
#pragma unroll
        for (int k = 0; k < 32; k++) {
            float av0 = sm->AL[ty * 2][sk + k];
            float av1 = sm->AL[ty * 2 + 1][sk + k];
            float4 x = *(const float4*)&sm->u.pb.Xs[bf][k][cb];
            accA.x = fmaf(av0, x.x, accA.x); accA.y = fmaf(av0, x.y, accA.y);
            accA.z = fmaf(av0, x.z, accA.z); accA.w = fmaf(av0, x.w, accA.w);
            accB.x = fmaf(av1, x.x, accB.x); accB.y = fmaf(av1, x.y, accB.y);
            accB.z = fmaf(av1, x.z, accB.z); accB.w = fmaf(av1, x.w, accB.w);
        }
        __syncthreads();
    }

    if (dok0)
        *(float4*)&agg[((size_t)bh * N_ + d0) * C_ + cb] = accA;
    if (dok1)
        *(float4*)&agg[((size_t)bh * N_ + d1) * C_ + cb] = accB;
}

// ---------------- fused xl/xr GEMM, cp.async double-buffered ----------------
__global__ __launch_bounds__(256) void gemm_dual(const float* __restrict__ A,
                                                 const float* __restrict__ B1,
                                                 const float* __restrict__ c1,
                                                 float* __restrict__ o1,
                                                 const float* __restrict__ B2,
                                                 const float* __restrict__ c2p,
                                                 float* __restrict__ o2,
                                                 int M, int K)
{
    __shared__ __align__(16) float As[2][64][36];
    __shared__ __align__(16) float Bs[2][32][36];

    const float* Bm;
    const float* bias;
    float* out;
    int n0;
    if (blockIdx.x < 32) { Bm = B1; bias = c1;  out = o1; n0 = blockIdx.x * 32; }
    else                 { Bm = B2; bias = c2p; out = o2; n0 = (blockIdx.x - 32) * 32; }

    int tid = threadIdx.x;
    int tx = tid & 15, ty = tid >> 4;
    int m0 = blockIdx.y * 64;

    int a_row = tid >> 2, a_c4a = (tid & 3) * 2;
    int b_row = tid >> 3, b_c4 = tid & 7;

    {
        bool okA = (m0 + a_row) < M;
        const float* srcA = &A[(size_t)(m0 + (okA ? a_row : 0)) * K + a_c4a * 4];
        cp16(s2u(&As[0][a_row][a_c4a * 4]), srcA, okA);
        cp16(s2u(&As[0][a_row][(a_c4a + 1) * 4]), srcA + 4, okA);
        cp16(s2u(&Bs[0][b_row][b_c4 * 4]),
             &Bm[(size_t)b_row * HC_ + n0 + b_c4 * 4], true);
    }
    cp_commit();

    float acc[4][2];
#pragma unroll
    for (int i = 0; i < 4; i++) { acc[i][0] = 0.f; acc[i][1] = 0.f; }

    int nch = K / 32;
#pragma unroll 1
    for (int ch = 0; ch < nch; ch++) {
        cp_wait0();
        __syncthreads();
        if (ch + 1 < nch) {
            int nb = (ch + 1) & 1;
            int kkn = (ch + 1) * 32;
            bool okA = (m0 + a_row) < M;
            const float* srcA = &A[(size_t)(m0 + (okA ? a_row : 0)) * K + kkn + a_c4a * 4];
            cp16(s2u(&As[nb][a_row][a_c4a * 4]), srcA, okA);
            cp16(s2u(&As[nb][a_row][(a_c4a + 1) * 4]), srcA + 4, okA);
            cp16(s2u(&Bs[nb][b_row][b_c4 * 4]),
                 &Bm[(size_t)(kkn + b_row) * HC_ + n0 + b_c4 * 4], true);
            cp_commit();
        }
        int bf = ch & 1;
#pragma unroll
        for (int k = 0; k < 32; k++) {
            float a0 = As[bf][ty * 4 + 0][k];
            float a1 = As[bf][ty * 4 + 1][k];
            float a2 = As[bf][ty * 4 + 2][k];
            float a3 = As[bf][ty * 4 + 3][k];
            float2 bv = *(const float2*)&Bs[bf][k][tx * 2];
            acc[0][0] = fmaf(a0, bv.x, acc[0][0]); acc[0][1] = fmaf(a0, bv.y, acc[0][1]);
            acc[1][0] = fmaf(a1, bv.x, acc[1][0]); acc[1][1] = fmaf(a1, bv.y, acc[1][1]);
            acc[2][0] = fmaf(a2, bv.x, acc[2][0]); acc[2][1] = fmaf(a2, bv.y, acc[2][1]);
            acc[3][0] = fmaf(a3, bv.x, acc[3][0]); acc[3][1] = fmaf(a3, bv.y, acc[3][1]);
        }
        __syncthreads();
    }

    float b0 = bias[n0 + tx * 2], b1 = bias[n0 + tx * 2 + 1];
#pragma unroll
    for (int i = 0; i < 4; i++) {
        int r = m0 + ty * 4 + i;
        if (r < M) {
            out[(size_t)r * HC_ + n0 + tx * 2]     = acc[i][0] + b0;
            out[(size_t)r * HC_ + n0 + tx * 2 + 1] = acc[i][1] + b1;
        }
    }
}

// ---------------- generic 32x32 GEMM, cp.async double-buffered --------------
// mode: 1 relu, 2 residual +=
__global__ void gemm_kernel(const float* __restrict__ A,
                            const float* __restrict__ Bm,
                            const float* __restrict__ bias,
                            float* __restrict__ out,
                            int M, int N, int K, int mode)
{
    __shared__ __align__(16) float As[2][32][36];
    __shared__ __align__(16) float Bs[2][32][36];
    int tid = threadIdx.x;
    int tx = tid & 15, ty = tid >> 4;
    int m0 = blockIdx.y * 32;
    int n0 = blockIdx.x * 32;
    int lr = tid >> 3, lc4 = tid & 7;
    float a00 = 0.f, a01 = 0.f, a10 = 0.f, a11 = 0.f;

    {
        bool okA = (m0 + lr) < M;
        cp16(s2u(&As[0][lr][lc4 * 4]),
             &A[(size_t)(m0 + (okA ? lr : 0)) * K + lc4 * 4], okA);
        cp16(s2u(&Bs[0][lr][lc4 * 4]),
             &Bm[(size_t)lr * N + n0 + lc4 * 4], true);
    }
    cp_commit();

    int nch = K / 32;
#pragma unroll 1
    for (int ch = 0; ch < nch; ch++) {
        cp_wait0();
        __syncthreads();
        if (ch + 1 < nch) {
            int nb = (ch + 1) & 1;
            int kkn = (ch + 1) * 32;
            bool okA = (m0 + lr) < M;
            cp16(s2u(&As[nb][lr][lc4 * 4]),
                 &A[(size_t)(m0 + (okA ? lr : 0)) * K + kkn + lc4 * 4], okA);
            cp16(s2u(&Bs[nb][lr][lc4 * 4]),
                 &Bm[(size_t)(kkn + lr) * N + n0 + lc4 * 4], true);
            cp_commit();
        }
        int bf = ch & 1;
#pragma unroll
        for (int k = 0; k < 32; k++) {
            float av0 = As[bf][ty][k],      av1 = As[bf][ty + 16][k];
            float bv0 = Bs[bf][k][tx],      bv1 = Bs[bf][k][tx + 16];
            a00 = fmaf(av0, bv0, a00);  a01 = fmaf(av0, bv1, a01);
            a10 = fmaf(av1, bv0, a10);  a11 = fmaf(av1, bv1, a11);
        }
        __syncthreads();
    }

    int r0 = m0 + ty, r1 = m0 + ty + 16;
    int c0 = n0 + tx, c1 = n0 + tx + 16;
    float b0 = bias[c0], b1 = bias[c1];
    if (mode == 1) {
        if (r0 < M) { out[r0 * N + c0] = fmaxf(a00 + b0, 0.f); out[r0 * N + c1] = fmaxf(a01 + b1, 0.f); }
        if (r1 < M) { out[r1 * N + c0] = fmaxf(a10 + b0, 0.f); out[r1 * N + c1] = fmaxf(a11 + b1, 0.f); }
    } else {
        if (r0 < M) { out[r0 * N + c0] += a00 + b0; out[r0 * N + c1] += a01 + b1; }
        if (r1 < M) { out[r1 * N + c0] += a10 + b0; out[r1 * N + c1] += a11 + b1; }
    }
}

// ---------------- head-mean + bias + layernorm (4 rows/block, float4) -------
__global__ __launch_bounds__(256) void ln_kernel(const float* __restrict__ agg,
                                                 const float* __restrict__ bias_l,
                                                 const float* __restrict__ g,
                                                 const float* __restrict__ bt,
                                                 float* __restrict__ out)
{
    int ty = threadIdx.x >> 6;
    int tx = threadIdx.x & 63;
    int wq = threadIdx.x >> 5;
    int n = blockIdx.x * 4 + ty;
    bool ok = n < NN_;
    int b = (n >= N_) ? 1 : 0;
    int d = n - b * N_;

    float4 v = make_float4(0.f, 0.f, 0.f, 0.f);
    if (ok) {
#pragma unroll
        for (int h = 0; h < H_; h++) {
            float4 t = *(const float4*)&agg[((size_t)(b * H_ + h) * N_ + d) * C_ + tx * 4];
            v.x += t.x; v.y += t.y; v.z += t.z; v.w += t.w;
        }
        float4 bb = *(const float4*)&bias_l[tx * 4];
        v.x = 0.25f * v.x + bb.x; v.y = 0.25f * v.y + bb.y;
        v.z = 0.25f * v.z + bb.z; v.w = 0.25f * v.w + bb.w;
    }

    __shared__ float red[8];
    float s = v.x + v.y + v.z + v.w;
#pragma unroll
    for (int o = 16; o; o >>= 1) s += __shfl_xor_sync(0xffffffffu, s, o);
    if ((threadIdx.x & 31) == 0) red[wq] = s;
    __syncthreads();
    float mu = (red[ty * 2] + red[ty * 2 + 1]) * (1.f / C_);
    __syncthreads();

    float4 dd = make_float4(v.x - mu, v.y - mu, v.z - mu, v.w - mu);
    float s2 = dd.x * dd.x + dd.y * dd.y + dd.z * dd.z + dd.w * dd.w;
#pragma unroll
    for (int o = 16; o; o >>= 1) s2 += __shfl_xor_sync(0xffffffffu, s2, o);
    if ((threadIdx.x & 31) == 0) red[wq] = s2;
    __syncthreads();
    float rstd = rsqrtf((red[ty * 2] + red[ty * 2 + 1]) * (1.f / C_) + 1e-5f);

    if (ok) {
        float4 gg = *(const float4*)&g[tx * 4];
        float4 tb = *(const float4*)&bt[tx * 4];
        float4 o4;
        o4.x = dd.x * rstd * gg.x + tb.x;
        o4.y = dd.y * rstd * gg.y + tb.y;
        o4.z = dd.z * rstd * gg.z + tb.z;
        o4.w = dd.w * rstd * gg.w + tb.w;
        *(float4*)&out[(size_t)n * C_ + tx * 4] = o4;
    }
}

// ---------------- final mean pool per graph ----------------------------------
__global__ void pool_kernel(const float* __restrict__ x, float* __restrict__ out)
{
    int b = blockIdx.x, t = threadIdx.x;
    float s = 0.f;
#pragma unroll 13
    for (int d = 0; d < N_; d++) s += x[(b * N_ + d) * C_ + t];
    out[b * C_ + t] = s * (1.f / N_);
}

__global__ void copy_kernel(const float* __restrict__ src, float* __restrict__ dst)
{
    int i = blockIdx.x * 256 + threadIdx.x;
    dst[i] = src[i];
}

// ---------------- host launcher -----------------------------------------------
extern "C" void kernel_launch(void* const* d_in, const int* in_sizes, int n_in,
                              void* d_out, int out_size)
{
    const float* x    = (const float*)d_in[0];
    const float* Wl   = (const float*)d_in[1];
    const float* bl   = (const float*)d_in[2];
    const float* Wr   = (const float*)d_in[3];
    const float* br   = (const float*)d_in[4];
    const float* att  = (const float*)d_in[5];
    const float* bias = (const float*)d_in[6];
    const float* lng  = (const float*)d_in[7];
    const float* lnb  = (const float*)d_in[8];
    const float* W1   = (const float*)d_in[9];
    const float* b1   = (const float*)d_in[10];
    const float* W2   = (const float*)d_in[11];
    const float* b2   = (const float*)d_in[12];

    float *bx, *bxl, *bxr, *bag, *bh, *bm, *bu, *bw;
    cudaGetSymbolAddress((void**)&bx,  g_x);
    cudaGetSymbolAddress((void**)&bxl, g_xl);
    cudaGetSymbolAddress((void**)&bxr, g_xr);
    cudaGetSymbolAddress((void**)&bag, g_agg);
    cudaGetSymbolAddress((void**)&bh,  g_h);
    cudaGetSymbolAddress((void**)&bm,  g_m);
    cudaGetSymbolAddress((void**)&bu,  g_u);
    cudaGetSymbolAddress((void**)&bw,  g_w);

    static int attr_done = 0;
    if (!attr_done) {
        cudaFuncSetAttribute(attn_agg_kernel,
                             cudaFuncAttributeMaxDynamicSharedMemorySize,
                             (int)ATTN_SMEM_BYTES);
        attr_done = 1;
    }

    copy_kernel<<<NN_, 256>>>(x, bx);

    for (int l = 0; l < L_; l++) {
        gemm_dual<<<dim3(64, 6), 256>>>(bx,
                                        Wl + l * C_ * HC_, bl + l * HC_, bxl,
                                        Wr + l * C_ * HC_, br + l * HC_, bxr,
                                        NN_, C_);
        uw_kernel<<<NN_, 128>>>(bxl, bxr, att + l * H_ * C_, bu, bw);
        attn_agg_kernel<<<dim3(43, 8), 128, ATTN_SMEM_BYTES>>>(
            bxl, bxr, att + l * H_ * C_, bu, bw, bag);
        ln_kernel<<<85, 256>>>(bag, bias + l * C_, lng + l * C_, lnb + l * C_, bh);
        gemm_kernel<<<dim3(16, 11), 256>>>(bh, W1 + l * C_ * 2 * C_, b1 + l * 2 * C_,
                                           bm, NN_, 2 * C_, C_, 1);
        gemm_kernel<<<dim3(8, 11), 256>>>(bm, W2 + l * 2 * C_ * C_, b2 + l * C_,
                                          bx, NN_, C_, 2 * C_, 2);
    }

    pool_kernel<<<B_, 256>>>(bx, (float*)d_out);
}